// round 11
// baseline (speedup 1.0000x reference)
#include <cuda_runtime.h>
#include <math.h>

#define L    48
#define LH   26                 // kept frequencies (Hermitian half: 0..25)
#define N3   110592             // 48^3
#define NHALF 55296             // N3/2
#define BF   128                // B*CIN  fields for x / Z
#define CF   256                // CIN*COUT fields for Y
#define PLH  59904              // 48*48*26

// ---------------- scratch (static device memory) ---------------------------
__device__ float2 g_tw[L * L];
__device__ float2 g_tw1[L];
__device__ float2 g_emp[L];
__device__ float2 g_bufB[BF * PLH];            // 61 MB intermediate
__device__ float  g_Xh[BF * N3];
__device__ float  g_Yh[CF * N3];
__device__ float  g_Z [BF * N3];
__device__ float2 g_T1[CF * 12 * 12 * L];

// ---------------- twiddle init ---------------------------------------------
__global__ void init_tw() {
    int idx = blockIdx.x * blockDim.x + threadIdx.x;
    if (idx < L * L) {
        int k = idx / L, n = idx % L;
        int m = (k * n) % L;
        double a = -6.283185307179586476925286766559 * (double)m / (double)L;
        g_tw[idx] = make_float2((float)cos(a), (float)sin(a));
    }
    if (idx < L) {
        double a = -6.283185307179586476925286766559 * (double)idx / (double)L;
        float cx = (float)cos(a), cy = (float)sin(a);
        g_tw1[idx] = make_float2(cx, cy);
        g_emp[idx] = make_float2(cx - cy, cx + cy);
    }
}

// ============ fused pass W+H: real plane -> half spectrum [k_h][k_w] ========
// Radix-8 stages: unit = (n2, j, k1-half) -> balanced, 8 accum regs.
// 6 blocks/SM target; 5 uniform barriers.
__global__ __launch_bounds__(256, 6) void pass_wh(
    const float* __restrict__ in, float2* __restrict__ out)
{
    __shared__ __align__(16) char ubuf[48 * 27 * sizeof(float2)];  // P / C overlay
    float  (*P)[50] = reinterpret_cast<float  (*)[50]>(ubuf);      // P[w][h] 9600B
    float2 (*C)[27] = reinterpret_cast<float2 (*)[27]>(ubuf);      // C[m_h][k_w]
    __shared__ float2 A2[L][L + 1];                                // 18816 B
    float2 (*B2)[49] = reinterpret_cast<float2 (*)[49]>(&A2[0][0]); // overlay
    __shared__ float2 TWs[L];

    int t = threadIdx.x;
    int f = blockIdx.x / L, d = blockIdx.x % L;
    const float* src = in + (size_t)f * N3 + (size_t)d * 2304;

    if (t < L) TWs[t] = g_tw1[t];
    for (int idx = t; idx < L * L; idx += 256)
        P[idx % L][idx / L] = src[idx];          // transpose: P[w][h]
    __syncthreads();                             // (1)

    float2 W8[8];
    #pragma unroll
    for (int u = 0; u < 8; u++) W8[u] = TWs[6 * u];

    int tx = t & 15, ty = t >> 4;
    int k1r = ty & 7;
    bool g1 = (tx < 10);
    int txg = g1 ? (tx + 16) : 0;

    // ---- stage 1 (w, real radix-8): 576 units = (n2, j, half-of-4-k1) ------
    for (int u = t; u < 576; u += 256) {
        int n2 = u / 96;
        int r  = u - n2 * 96;
        int j  = r >> 1;
        int hf = (r & 1) * 4;
        float ar[4] = {0,0,0,0}, ai[4] = {0,0,0,0};
        #pragma unroll
        for (int n1 = 0; n1 < 8; n1++) {
            float p = P[6 * n1 + n2][j];
            #pragma unroll
            for (int q = 0; q < 4; q++) {
                float2 w = W8[(n1 * (hf + q)) & 7];
                ar[q] += p * w.x;  ai[q] += p * w.y;
            }
        }
        #pragma unroll
        for (int q = 0; q < 4; q++)
            A2[n2 * 8 + hf + q][j] = make_float2(ar[q], ai[q]);
    }
    __syncthreads();                             // (2)

    // ---- stage 2 (w, radix-6): k_w = tx+16c (<26), h = ty+16a ---------------
    {
        float xr[3][2] = {{0.f}}, xi[3][2] = {{0.f}};
        int r8 = tx & 7;
        int i0 = 0, i1 = 0;
        int k3a = tx, k3b = tx + 16;
        #pragma unroll
        for (int n2 = 0; n2 < 6; n2++) {
            int arow = n2 * 8 + r8;
            float2 w0 = TWs[i0], w1 = TWs[i1];
            i0 += k3a; if (i0 >= L) i0 -= L;
            i1 += k3b; if (i1 >= L) i1 -= L;
            #pragma unroll
            for (int a = 0; a < 3; a++) {
                float2 v = A2[arow][ty + 16 * a];
                xr[a][0] += v.x * w0.x - v.y * w0.y;
                xi[a][0] += v.x * w0.y + v.y * w0.x;
                xr[a][1] += v.x * w1.x - v.y * w1.y;
                xi[a][1] += v.x * w1.y + v.y * w1.x;
            }
        }
        __syncthreads();                         // (3) A2 reads done; B2 overlays
        #pragma unroll
        for (int a = 0; a < 3; a++) {
            int h = ty + 16 * a;
            B2[k3a][h] = make_float2(xr[a][0], xi[a][0]);
            if (g1) B2[k3b][h] = make_float2(xr[a][1], xi[a][1]);
        }
    }
    __syncthreads();                             // (4)

    // ---- stage 3 (h, complex radix-8): 312 units = (n2, k_w, half) ---------
    // C overlays P, whose last reads were fenced by barrier (2): no pre-barrier.
    for (int u = t; u < 312; u += 256) {
        int n2 = u / 52;
        int r  = u - n2 * 52;
        int kw = r >> 1;
        int hf = (r & 1) * 4;
        float cr[4] = {0,0,0,0}, ci[4] = {0,0,0,0};
        #pragma unroll
        for (int n1 = 0; n1 < 8; n1++) {
            float2 q = B2[kw][6 * n1 + n2];
            #pragma unroll
            for (int qq = 0; qq < 4; qq++) {
                float2 w = W8[(n1 * (hf + qq)) & 7];
                cr[qq] += q.x * w.x - q.y * w.y;
                ci[qq] += q.x * w.y + q.y * w.x;
            }
        }
        #pragma unroll
        for (int qq = 0; qq < 4; qq++)
            C[n2 * 8 + hf + qq][kw] = make_float2(cr[qq], ci[qq]);
    }
    __syncthreads();                             // (5)

    // ---- stage 4 (h, radix-6): out[k_h][k_w] --------------------------------
    {
        float xr[3][2] = {{0.f}}, xi[3][2] = {{0.f}};
        int iw[3] = {0, 0, 0};
        #pragma unroll
        for (int n2 = 0; n2 < 6; n2++) {
            int arow = n2 * 8 + k1r;
            float2 v0 = C[arow][tx];
            float2 v1 = C[arow][txg];
            #pragma unroll
            for (int a = 0; a < 3; a++) {
                float2 w = TWs[iw[a]];
                iw[a] += ty + 16 * a; if (iw[a] >= L) iw[a] -= L;
                xr[a][0] += v0.x * w.x - v0.y * w.y;
                xi[a][0] += v0.x * w.y + v0.y * w.x;
                xr[a][1] += v1.x * w.x - v1.y * w.y;
                xi[a][1] += v1.x * w.y + v1.y * w.x;
            }
        }
        float2* dst = out + (size_t)(f * L + d) * (L * LH);
        #pragma unroll
        for (int a = 0; a < 3; a++) {
            int k2 = ty + 16 * a;
            dst[(size_t)k2 * LH + tx] = make_float2(xr[a][0], xi[a][0]);
            if (g1) dst[(size_t)k2 * LH + tx + 16] = make_float2(xr[a][1], xi[a][1]);
        }
    }
}

// ============ pass D: complex, DFT along d, fold + Hermitian mirror write ===
__global__ __launch_bounds__(256, 6) void pass_d(
    const float2* __restrict__ in, float* __restrict__ out, float scale)
{
    __shared__ float2 Q2[L][LH + 1];
    __shared__ float2 A2[L][LH + 1];
    __shared__ float2 TWs[L];
    int t = threadIdx.x;
    int f = blockIdx.x / L, k2 = blockIdx.x % L;
    const float2* src = in + ((size_t)f * (L * L) + k2) * LH;

    if (t < L) TWs[t] = g_tw1[t];
    for (int idx = t; idx < L * LH; idx += 256)
        Q2[idx / LH][idx % LH] = src[(size_t)(idx / LH) * (L * LH) + (idx % LH)];
    __syncthreads();

    float2 W8[8];
    #pragma unroll
    for (int u = 0; u < 8; u++) W8[u] = TWs[6 * u];

    int tx = t & 15, ty = t >> 4;
    bool g1 = (tx < 10);
    int txg = g1 ? (tx + 16) : 0;

    // ---- stage 1 (d, complex radix-8): 312 units = (n2, k_w, half) ----------
    for (int u = t; u < 312; u += 256) {
        int n2 = u / 52;
        int r  = u - n2 * 52;
        int kw = r >> 1;
        int hf = (r & 1) * 4;
        float cr[4] = {0,0,0,0}, ci[4] = {0,0,0,0};
        #pragma unroll
        for (int n1 = 0; n1 < 8; n1++) {
            float2 q = Q2[6 * n1 + n2][kw];
            #pragma unroll
            for (int qq = 0; qq < 4; qq++) {
                float2 w = W8[(n1 * (hf + qq)) & 7];
                cr[qq] += q.x * w.x - q.y * w.y;
                ci[qq] += q.x * w.y + q.y * w.x;
            }
        }
        #pragma unroll
        for (int qq = 0; qq < 4; qq++)
            A2[n2 * 8 + hf + qq][kw] = make_float2(cr[qq], ci[qq]);
    }
    __syncthreads();

    // ---- stage 2 (d, radix-6) + fold/mirror ---------------------------------
    {
        int r8 = ty & 7;
        float xr[3][2] = {{0.f}}, xi[3][2] = {{0.f}};
        int iw[3] = {0, 0, 0};
        #pragma unroll
        for (int n2 = 0; n2 < 6; n2++) {
            int arow = n2 * 8 + r8;
            float2 v0 = A2[arow][tx];
            float2 v1 = A2[arow][txg];
            #pragma unroll
            for (int a = 0; a < 3; a++) {
                float2 w = TWs[iw[a]];
                iw[a] += ty + 16 * a; if (iw[a] >= L) iw[a] -= L;
                xr[a][0] += v0.x * w.x - v0.y * w.y;
                xi[a][0] += v0.x * w.y + v0.y * w.x;
                xr[a][1] += v1.x * w.x - v1.y * w.y;
                xi[a][1] += v1.x * w.y + v1.y * w.x;
            }
        }
        int mk2 = (k2 == 0) ? 0 : L - k2;
        float* dstD = out + (size_t)f * N3 + (size_t)k2 * L;
        float* dstM = out + (size_t)f * N3 + (size_t)mk2 * L;
        int k3a = tx, k3b = tx + 16;
        int m3a = (k3a == 0) ? 0 : L - k3a;
        int m3b = L - k3b;
        #pragma unroll
        for (int a = 0; a < 3; a++) {
            int k1 = ty + 16 * a;
            int mk1 = (k1 == 0) ? 0 : L - k1;
            dstD[(size_t)k1 * 2304 + k3a]  = scale * (xr[a][0] - xi[a][0]);
            dstM[(size_t)mk1 * 2304 + m3a] = scale * (xr[a][0] + xi[a][0]);
            if (g1) {
                dstD[(size_t)k1 * 2304 + k3b]  = scale * (xr[a][1] - xi[a][1]);
                dstM[(size_t)mk1 * 2304 + m3b] = scale * (xr[a][1] + xi[a][1]);
            }
        }
    }
}

// ---------------- Y path -----------------------------------------------------
__global__ void ykernel1(const float* __restrict__ w) {
    int idx = blockIdx.x * blockDim.x + threadIdx.x;
    if (idx >= CF * 12 * 12 * L) return;
    int k3 = idx % L;
    int r  = idx / L;
    const float* wp = w + r * 12;
    float ar = 0.f, ai = 0.f;
    #pragma unroll
    for (int n3 = 0; n3 < 12; n3++) {
        float2 e = g_tw[k3 * L + n3];
        float  v = wp[n3];
        ar += v * e.x;  ai += v * e.y;
    }
    g_T1[idx] = make_float2(ar, ai);
}

// fused ykernel2 + ykernel3 (per io, quarter of k2); T1 slice in dynamic smem.
__global__ __launch_bounds__(256) void ykernel23() {
    extern __shared__ float2 ysm[];
    float2* T1s = ysm;                      // 6912 float2
    float2* T2c = ysm + 6912;               // [n1*49 + k3]
    __shared__ float2 TWs[L];
    __shared__ float2 EMPs[L];

    int t  = threadIdx.x;
    int io = blockIdx.x >> 2;
    int kt = blockIdx.x & 3;

    if (t < L) { TWs[t] = g_tw1[t]; EMPs[t] = g_emp[t]; }
    const float2* src = g_T1 + (size_t)io * 6912;
    for (int idx = t; idx < 6912; idx += 256) T1s[idx] = src[idx];
    __syncthreads();

    int tx = t & 15, ty = t >> 4;

    for (int kk = 0; kk < 12; kk++) {
        int k2 = kt * 12 + kk;

        for (int idx = t; idx < 576; idx += 256) {
            int n1 = idx / 48, k3 = idx - n1 * 48;
            const float2* tp = T1s + n1 * 576 + k3;
            float ar = 0.f, ai = 0.f;
            int iw = 0;
            #pragma unroll
            for (int n2 = 0; n2 < 12; n2++) {
                float2 v = tp[n2 * 48];
                float2 e = TWs[iw];
                iw += k2; if (iw >= L) iw -= L;
                ar += v.x * e.x - v.y * e.y;
                ai += v.x * e.y + v.y * e.x;
            }
            T2c[n1 * 49 + k3] = make_float2(ar, ai);
        }
        __syncthreads();

        {
            float acc[3][3] = {{0.f}};
            int iw2[3] = {0, 0, 0};
            #pragma unroll
            for (int n1 = 0; n1 < 12; n1++) {
                float2 tv[3];
                #pragma unroll
                for (int b = 0; b < 3; b++) tv[b] = T2c[n1 * 49 + tx + 16 * b];
                #pragma unroll
                for (int a = 0; a < 3; a++) {
                    float2 e = EMPs[iw2[a]];
                    iw2[a] += ty + 16 * a; if (iw2[a] >= L) iw2[a] -= L;
                    #pragma unroll
                    for (int b = 0; b < 3; b++)
                        acc[a][b] += tv[b].x * e.x - tv[b].y * e.y;
                }
            }
            #pragma unroll
            for (int a = 0; a < 3; a++)
                #pragma unroll
                for (int b = 0; b < 3; b++)
                    g_Yh[(size_t)io * N3 + (size_t)(ty + 16 * a) * 2304
                         + (size_t)k2 * 48 + tx + 16 * b] = acc[a][b];
        }
        __syncthreads();
    }
}

// ---------------- coalesced paired mix (MK=8, 36KB smem) ---------------------
#define MK    8
#define MPIT  12
__global__ __launch_bounds__(256) void mix3() {
    extern __shared__ float sm[];
    float* Xa = sm;                        // [128][MPIT]
    float* Xb = Xa + 128 * MPIT;
    float* Ya = Xb + 128 * MPIT;           // [256][MPIT]
    float* Yb = Ya + 256 * MPIT;

    int t  = threadIdx.x;
    int k0 = blockIdx.x * MK;

    for (int q = t; q < 128 * MK; q += 256) {
        int kk = q & 7, bi = q >> 3;
        int k = k0 + kk; if (k > NHALF) k = NHALF;
        int sk = (k == 0) ? 0 : (N3 - k);
        Xa[bi * MPIT + kk] = g_Xh[(size_t)bi * N3 + k];
        Xb[bi * MPIT + kk] = g_Xh[(size_t)bi * N3 + sk];
    }
    for (int q = t; q < 256 * MK; q += 256) {
        int kk = q & 7, io = q >> 3;
        int k = k0 + kk; if (k > NHALF) k = NHALF;
        int sk = (k == 0) ? 0 : (N3 - k);
        Ya[io * MPIT + kk] = g_Yh[(size_t)io * N3 + k];
        Yb[io * MPIT + kk] = g_Yh[(size_t)io * N3 + sk];
    }
    __syncthreads();

    int kh = t >> 7;                       // 0/1: k offset kh*4
    int b  = (t >> 4) & 7;
    int o  = t & 15;

    float acc[4] = {0,0,0,0}, accs[4] = {0,0,0,0};
    #pragma unroll 4
    for (int i = 0; i < 16; i++) {
        const float* xa = Xa + (b * 16 + i) * MPIT + kh * 4;
        const float* xb = Xb + (b * 16 + i) * MPIT + kh * 4;
        const float* ya = Ya + (i * 16 + o) * MPIT + kh * 4;
        const float* yb = Yb + (i * 16 + o) * MPIT + kh * 4;
        float xk[4], xs[4], yk[4], ys[4];
        *(float4*)&xk[0] = *(const float4*)xa;
        *(float4*)&xs[0] = *(const float4*)xb;
        *(float4*)&yk[0] = *(const float4*)ya;
        *(float4*)&ys[0] = *(const float4*)yb;
        #pragma unroll
        for (int kk = 0; kk < 4; kk++) {
            float xe = 0.5f * (xk[kk] + xs[kk]);
            float xo = 0.5f * (xk[kk] - xs[kk]);
            acc[kk]  += xe * yk[kk] + xo * ys[kk];
            accs[kk] += xe * ys[kk] - xo * yk[kk];
        }
    }

    int kb = k0 + kh * 4;
    float* zrow = g_Z + (size_t)(b * 16 + o) * N3;
    if (kb + 3 <= NHALF) {
        *(float4*)(zrow + kb) = make_float4(acc[0], acc[1], acc[2], acc[3]);
    } else {
        #pragma unroll
        for (int kk = 0; kk < 4; kk++)
            if (kb + kk <= NHALF) zrow[kb + kk] = acc[kk];
    }
    #pragma unroll
    for (int kk = 0; kk < 4; kk++) {
        int k = kb + kk;
        if (k >= 1 && k <= NHALF - 1) zrow[N3 - k] = accs[kk];
    }
}

// ---------------- launcher ----------------------------------------------------
extern "C" void kernel_launch(void* const* d_in, const int* in_sizes, int n_in,
                              void* d_out, int out_size) {
    (void)in_sizes; (void)n_in; (void)out_size;
    static float2* bufB = nullptr;
    static float*  xh   = nullptr;
    static float*  z    = nullptr;
    if (!bufB) {
        cudaGetSymbolAddress((void**)&bufB, g_bufB);
        cudaGetSymbolAddress((void**)&xh,   g_Xh);
        cudaGetSymbolAddress((void**)&z,    g_Z);
        cudaFuncSetAttribute(mix3, cudaFuncAttributeMaxDynamicSharedMemorySize,
                             (128 * MPIT * 2 + 256 * MPIT * 2) * (int)sizeof(float));
        cudaFuncSetAttribute(ykernel23, cudaFuncAttributeMaxDynamicSharedMemorySize,
                             (6912 + 12 * 49) * (int)sizeof(float2));
    }
    const float* x  = (const float*)d_in[0];   // [8,16,48,48,48]
    const float* wt = (const float*)d_in[2];   // [16,16,12,12,12]
    float* out = (float*)d_out;

    const int mix_smem = (128 * MPIT * 2 + 256 * MPIT * 2) * (int)sizeof(float);
    const int mix_grid = NHALF / MK + 1;
    const int y_smem   = (6912 + 12 * 49) * (int)sizeof(float2);

    init_tw<<<(L * L + 255) / 256, 256>>>();

    ykernel1<<<(CF * 12 * 12 * L + 255) / 256, 256>>>(wt);
    ykernel23<<<CF * 4, 256, y_smem>>>();

    // forward: x -> Xh
    pass_wh<<<BF * L, 256>>>(x, bufB);
    pass_d <<<BF * L, 256>>>(bufB, xh, 1.f);

    mix3<<<mix_grid, 256, mix_smem>>>();

    // inverse: Z -> out (scaled 1/N3)
    pass_wh<<<BF * L, 256>>>(z, bufB);
    pass_d <<<BF * L, 256>>>(bufB, out, 1.f / (float)N3);
}

// round 12
// speedup vs baseline: 1.0544x; 1.0544x over previous
#include <cuda_runtime.h>
#include <math.h>

#define L    48
#define LH   26                 // kept frequencies (Hermitian half: 0..25)
#define N3   110592             // 48^3
#define NHALF 55296             // N3/2
#define BF   128                // B*CIN  fields for x / Z
#define CF   256                // CIN*COUT fields for Y
#define PLH  59904              // 48*48*26

// ---------------- scratch (static device memory) ---------------------------
__device__ float2 g_tw[L * L];
__device__ float2 g_tw1[L];
__device__ float2 g_emp[L];
__device__ float2 g_bufB[BF * PLH];            // 61 MB intermediate
__device__ float  g_Xh[BF * N3];
__device__ float  g_Yh[CF * N3];
__device__ float  g_Z [BF * N3];
__device__ float2 g_T1[CF * 12 * 12 * L];

// ---------------- twiddle init ---------------------------------------------
__global__ void init_tw() {
    int idx = blockIdx.x * blockDim.x + threadIdx.x;
    if (idx < L * L) {
        int k = idx / L, n = idx % L;
        int m = (k * n) % L;
        double a = -6.283185307179586476925286766559 * (double)m / (double)L;
        g_tw[idx] = make_float2((float)cos(a), (float)sin(a));
    }
    if (idx < L) {
        double a = -6.283185307179586476925286766559 * (double)idx / (double)L;
        float cx = (float)cos(a), cy = (float)sin(a);
        g_tw1[idx] = make_float2(cx, cy);
        g_emp[idx] = make_float2(cx - cy, cx + cy);
    }
}

// ============ fused pass W+H: real plane -> half spectrum [k_h][k_w] ========
// (R10 version: outer-product radix-8, 16 accums, 48 regs, 5 blocks/SM)
__global__ __launch_bounds__(256, 5) void pass_wh(
    const float* __restrict__ in, float2* __restrict__ out)
{
    __shared__ __align__(16) char ubuf[48 * 27 * sizeof(float2)];  // P / C overlay
    float  (*P)[50] = reinterpret_cast<float  (*)[50]>(ubuf);      // P[w][h] 9600B
    float2 (*C)[27] = reinterpret_cast<float2 (*)[27]>(ubuf);      // C[m_h][k_w]
    __shared__ float2 A2[L][L + 1];                                // 18816 B
    float2 (*B2)[49] = reinterpret_cast<float2 (*)[49]>(&A2[0][0]); // overlay
    __shared__ float2 TWs[L];

    int t = threadIdx.x;
    int f = blockIdx.x / L, d = blockIdx.x % L;
    const float* src = in + (size_t)f * N3 + (size_t)d * 2304;

    if (t < L) TWs[t] = g_tw1[t];
    for (int idx = t; idx < L * L; idx += 256)
        P[idx % L][idx / L] = src[idx];          // transpose: P[w][h]
    __syncthreads();

    float2 W8[8];
    #pragma unroll
    for (int u = 0; u < 8; u++) W8[u] = TWs[6 * u];

    int tx = t & 15, ty = t >> 4;
    int k1r = ty & 7;
    bool g1 = (tx < 10);
    int txg = g1 ? (tx + 16) : 0;

    // ---- stage 1 (w, real radix-8): A[n2*8+k1][j] for all k1 ---------------
    for (int u = t; u < 6 * 48; u += 256) {
        int n2 = u / 48, j = u - n2 * 48;
        float ar[8] = {0,0,0,0,0,0,0,0}, ai[8] = {0,0,0,0,0,0,0,0};
        #pragma unroll
        for (int n1 = 0; n1 < 8; n1++) {
            float p = P[6 * n1 + n2][j];
            #pragma unroll
            for (int k1 = 0; k1 < 8; k1++) {
                float2 w = W8[(n1 * k1) & 7];
                ar[k1] += p * w.x;  ai[k1] += p * w.y;
            }
        }
        #pragma unroll
        for (int k1 = 0; k1 < 8; k1++)
            A2[n2 * 8 + k1][j] = make_float2(ar[k1], ai[k1]);
    }
    __syncthreads();

    // ---- stage 2 (w, radix-6): k_w = tx+16c (<26), h = ty+16a ---------------
    {
        float xr[3][2] = {{0.f}}, xi[3][2] = {{0.f}};
        int r8 = tx & 7;
        int i0 = 0, i1 = 0;
        int k3a = tx, k3b = tx + 16;
        #pragma unroll
        for (int n2 = 0; n2 < 6; n2++) {
            int arow = n2 * 8 + r8;
            float2 w0 = TWs[i0], w1 = TWs[i1];
            i0 += k3a; if (i0 >= L) i0 -= L;
            i1 += k3b; if (i1 >= L) i1 -= L;
            #pragma unroll
            for (int a = 0; a < 3; a++) {
                float2 v = A2[arow][ty + 16 * a];
                xr[a][0] += v.x * w0.x - v.y * w0.y;
                xi[a][0] += v.x * w0.y + v.y * w0.x;
                xr[a][1] += v.x * w1.x - v.y * w1.y;
                xi[a][1] += v.x * w1.y + v.y * w1.x;
            }
        }
        __syncthreads();                         // A2 reads complete; B2 overlays it
        #pragma unroll
        for (int a = 0; a < 3; a++) {
            int h = ty + 16 * a;
            B2[k3a][h] = make_float2(xr[a][0], xi[a][0]);
            if (g1) B2[k3b][h] = make_float2(xr[a][1], xi[a][1]);
        }
    }
    __syncthreads();

    // ---- stage 3 (h, complex radix-8): C[n2*8+k1][k_w], thread = (n2,k_w) ---
    {
        bool act = (t < 6 * 26);
        int n2 = 0, kw = 0;
        float cr[8] = {0,0,0,0,0,0,0,0}, ci[8] = {0,0,0,0,0,0,0,0};
        if (act) {
            n2 = t / 26;  kw = t - n2 * 26;
            #pragma unroll
            for (int n1 = 0; n1 < 8; n1++) {
                float2 q = B2[kw][6 * n1 + n2];
                #pragma unroll
                for (int k1 = 0; k1 < 8; k1++) {
                    float2 w = W8[(n1 * k1) & 7];
                    cr[k1] += q.x * w.x - q.y * w.y;
                    ci[k1] += q.x * w.y + q.y * w.x;
                }
            }
        }
        __syncthreads();                         // uniform: B2 reads done, ubuf dead
        if (act) {
            #pragma unroll
            for (int k1 = 0; k1 < 8; k1++)
                C[n2 * 8 + k1][kw] = make_float2(cr[k1], ci[k1]);
        }
    }
    __syncthreads();

    // ---- stage 4 (h, radix-6): out[k_h][k_w] --------------------------------
    {
        float xr[3][2] = {{0.f}}, xi[3][2] = {{0.f}};
        int iw[3] = {0, 0, 0};
        #pragma unroll
        for (int n2 = 0; n2 < 6; n2++) {
            int arow = n2 * 8 + k1r;
            float2 v0 = C[arow][tx];
            float2 v1 = C[arow][txg];
            #pragma unroll
            for (int a = 0; a < 3; a++) {
                float2 w = TWs[iw[a]];
                iw[a] += ty + 16 * a; if (iw[a] >= L) iw[a] -= L;
                xr[a][0] += v0.x * w.x - v0.y * w.y;
                xi[a][0] += v0.x * w.y + v0.y * w.x;
                xr[a][1] += v1.x * w.x - v1.y * w.y;
                xi[a][1] += v1.x * w.y + v1.y * w.x;
            }
        }
        float2* dst = out + (size_t)(f * L + d) * (L * LH);
        #pragma unroll
        for (int a = 0; a < 3; a++) {
            int k2 = ty + 16 * a;
            dst[(size_t)k2 * LH + tx] = make_float2(xr[a][0], xi[a][0]);
            if (g1) dst[(size_t)k2 * LH + tx + 16] = make_float2(xr[a][1], xi[a][1]);
        }
    }
}

// ============ pass D: complex, DFT along d, fold + Hermitian mirror write ===
__global__ __launch_bounds__(256, 5) void pass_d(
    const float2* __restrict__ in, float* __restrict__ out, float scale)
{
    __shared__ float2 Q2[L][LH + 1];
    __shared__ float2 A2[L][LH + 1];
    __shared__ float2 TWs[L];
    int t = threadIdx.x;
    int f = blockIdx.x / L, k2 = blockIdx.x % L;
    const float2* src = in + ((size_t)f * (L * L) + k2) * LH;

    if (t < L) TWs[t] = g_tw1[t];
    for (int idx = t; idx < L * LH; idx += 256)
        Q2[idx / LH][idx % LH] = src[(size_t)(idx / LH) * (L * LH) + (idx % LH)];
    __syncthreads();

    float2 W8[8];
    #pragma unroll
    for (int u = 0; u < 8; u++) W8[u] = TWs[6 * u];

    int tx = t & 15, ty = t >> 4;
    bool g1 = (tx < 10);
    int txg = g1 ? (tx + 16) : 0;

    // ---- stage 1 (d, complex radix-8): thread = (n2, k_w), barrier uniform --
    if (t < 6 * 26) {
        int n2 = t / 26, kw = t - n2 * 26;
        float cr[8] = {0,0,0,0,0,0,0,0}, ci[8] = {0,0,0,0,0,0,0,0};
        #pragma unroll
        for (int n1 = 0; n1 < 8; n1++) {
            float2 q = Q2[6 * n1 + n2][kw];
            #pragma unroll
            for (int k1 = 0; k1 < 8; k1++) {
                float2 w = W8[(n1 * k1) & 7];
                cr[k1] += q.x * w.x - q.y * w.y;
                ci[k1] += q.x * w.y + q.y * w.x;
            }
        }
        #pragma unroll
        for (int k1 = 0; k1 < 8; k1++)
            A2[n2 * 8 + k1][kw] = make_float2(cr[k1], ci[k1]);
    }
    __syncthreads();

    // ---- stage 2 (d, radix-6) + fold/mirror ---------------------------------
    {
        int r8 = ty & 7;
        float xr[3][2] = {{0.f}}, xi[3][2] = {{0.f}};
        int iw[3] = {0, 0, 0};
        #pragma unroll
        for (int n2 = 0; n2 < 6; n2++) {
            int arow = n2 * 8 + r8;
            float2 v0 = A2[arow][tx];
            float2 v1 = A2[arow][txg];
            #pragma unroll
            for (int a = 0; a < 3; a++) {
                float2 w = TWs[iw[a]];
                iw[a] += ty + 16 * a; if (iw[a] >= L) iw[a] -= L;
                xr[a][0] += v0.x * w.x - v0.y * w.y;
                xi[a][0] += v0.x * w.y + v0.y * w.x;
                xr[a][1] += v1.x * w.x - v1.y * w.y;
                xi[a][1] += v1.x * w.y + v1.y * w.x;
            }
        }
        int mk2 = (k2 == 0) ? 0 : L - k2;
        float* dstD = out + (size_t)f * N3 + (size_t)k2 * L;
        float* dstM = out + (size_t)f * N3 + (size_t)mk2 * L;
        int k3a = tx, k3b = tx + 16;
        int m3a = (k3a == 0) ? 0 : L - k3a;
        int m3b = L - k3b;
        #pragma unroll
        for (int a = 0; a < 3; a++) {
            int k1 = ty + 16 * a;
            int mk1 = (k1 == 0) ? 0 : L - k1;
            dstD[(size_t)k1 * 2304 + k3a]  = scale * (xr[a][0] - xi[a][0]);
            dstM[(size_t)mk1 * 2304 + m3a] = scale * (xr[a][0] + xi[a][0]);
            if (g1) {
                dstD[(size_t)k1 * 2304 + k3b]  = scale * (xr[a][1] - xi[a][1]);
                dstM[(size_t)mk1 * 2304 + m3b] = scale * (xr[a][1] + xi[a][1]);
            }
        }
    }
}

// ---------------- Y path -----------------------------------------------------
__global__ void ykernel1(const float* __restrict__ w) {
    int idx = blockIdx.x * blockDim.x + threadIdx.x;
    if (idx >= CF * 12 * 12 * L) return;
    int k3 = idx % L;
    int r  = idx / L;
    const float* wp = w + r * 12;
    float ar = 0.f, ai = 0.f;
    #pragma unroll
    for (int n3 = 0; n3 < 12; n3++) {
        float2 e = g_tw[k3 * L + n3];
        float  v = wp[n3];
        ar += v * e.x;  ai += v * e.y;
    }
    g_T1[idx] = make_float2(ar, ai);
}

// fused ykernel2 + ykernel3 (per io, quarter of k2); T1 slice in dynamic smem.
__global__ __launch_bounds__(256) void ykernel23() {
    extern __shared__ float2 ysm[];
    float2* T1s = ysm;                      // 6912 float2
    float2* T2c = ysm + 6912;               // [n1*49 + k3]
    __shared__ float2 TWs[L];
    __shared__ float2 EMPs[L];

    int t  = threadIdx.x;
    int io = blockIdx.x >> 2;
    int kt = blockIdx.x & 3;

    if (t < L) { TWs[t] = g_tw1[t]; EMPs[t] = g_emp[t]; }
    const float2* src = g_T1 + (size_t)io * 6912;
    for (int idx = t; idx < 6912; idx += 256) T1s[idx] = src[idx];
    __syncthreads();

    int tx = t & 15, ty = t >> 4;

    for (int kk = 0; kk < 12; kk++) {
        int k2 = kt * 12 + kk;

        for (int idx = t; idx < 576; idx += 256) {
            int n1 = idx / 48, k3 = idx - n1 * 48;
            const float2* tp = T1s + n1 * 576 + k3;
            float ar = 0.f, ai = 0.f;
            int iw = 0;
            #pragma unroll
            for (int n2 = 0; n2 < 12; n2++) {
                float2 v = tp[n2 * 48];
                float2 e = TWs[iw];
                iw += k2; if (iw >= L) iw -= L;
                ar += v.x * e.x - v.y * e.y;
                ai += v.x * e.y + v.y * e.x;
            }
            T2c[n1 * 49 + k3] = make_float2(ar, ai);
        }
        __syncthreads();

        {
            float acc[3][3] = {{0.f}};
            int iw2[3] = {0, 0, 0};
            #pragma unroll
            for (int n1 = 0; n1 < 12; n1++) {
                float2 tv[3];
                #pragma unroll
                for (int b = 0; b < 3; b++) tv[b] = T2c[n1 * 49 + tx + 16 * b];
                #pragma unroll
                for (int a = 0; a < 3; a++) {
                    float2 e = EMPs[iw2[a]];
                    iw2[a] += ty + 16 * a; if (iw2[a] >= L) iw2[a] -= L;
                    #pragma unroll
                    for (int b = 0; b < 3; b++)
                        acc[a][b] += tv[b].x * e.x - tv[b].y * e.y;
                }
            }
            #pragma unroll
            for (int a = 0; a < 3; a++)
                #pragma unroll
                for (int b = 0; b < 3; b++)
                    g_Yh[(size_t)io * N3 + (size_t)(ty + 16 * a) * 2304
                         + (size_t)k2 * 48 + tx + 16 * b] = acc[a][b];
        }
        __syncthreads();
    }
}

// ---------------- coalesced paired mix (MK=8, 36KB smem) ---------------------
#define MK    8
#define MPIT  12
__global__ __launch_bounds__(256) void mix3() {
    extern __shared__ float sm[];
    float* Xa = sm;                        // [128][MPIT]
    float* Xb = Xa + 128 * MPIT;
    float* Ya = Xb + 128 * MPIT;           // [256][MPIT]
    float* Yb = Ya + 256 * MPIT;

    int t  = threadIdx.x;
    int k0 = blockIdx.x * MK;

    for (int q = t; q < 128 * MK; q += 256) {
        int kk = q & 7, bi = q >> 3;
        int k = k0 + kk; if (k > NHALF) k = NHALF;
        int sk = (k == 0) ? 0 : (N3 - k);
        Xa[bi * MPIT + kk] = g_Xh[(size_t)bi * N3 + k];
        Xb[bi * MPIT + kk] = g_Xh[(size_t)bi * N3 + sk];
    }
    for (int q = t; q < 256 * MK; q += 256) {
        int kk = q & 7, io = q >> 3;
        int k = k0 + kk; if (k > NHALF) k = NHALF;
        int sk = (k == 0) ? 0 : (N3 - k);
        Ya[io * MPIT + kk] = g_Yh[(size_t)io * N3 + k];
        Yb[io * MPIT + kk] = g_Yh[(size_t)io * N3 + sk];
    }
    __syncthreads();

    int kh = t >> 7;                       // 0/1: k offset kh*4
    int b  = (t >> 4) & 7;
    int o  = t & 15;

    float acc[4] = {0,0,0,0}, accs[4] = {0,0,0,0};
    #pragma unroll 4
    for (int i = 0; i < 16; i++) {
        const float* xa = Xa + (b * 16 + i) * MPIT + kh * 4;
        const float* xb = Xb + (b * 16 + i) * MPIT + kh * 4;
        const float* ya = Ya + (i * 16 + o) * MPIT + kh * 4;
        const float* yb = Yb + (i * 16 + o) * MPIT + kh * 4;
        float xk[4], xs[4], yk[4], ys[4];
        *(float4*)&xk[0] = *(const float4*)xa;
        *(float4*)&xs[0] = *(const float4*)xb;
        *(float4*)&yk[0] = *(const float4*)ya;
        *(float4*)&ys[0] = *(const float4*)yb;
        #pragma unroll
        for (int kk = 0; kk < 4; kk++) {
            float xe = 0.5f * (xk[kk] + xs[kk]);
            float xo = 0.5f * (xk[kk] - xs[kk]);
            acc[kk]  += xe * yk[kk] + xo * ys[kk];
            accs[kk] += xe * ys[kk] - xo * yk[kk];
        }
    }

    int kb = k0 + kh * 4;
    float* zrow = g_Z + (size_t)(b * 16 + o) * N3;
    if (kb + 3 <= NHALF) {
        *(float4*)(zrow + kb) = make_float4(acc[0], acc[1], acc[2], acc[3]);
    } else {
        #pragma unroll
        for (int kk = 0; kk < 4; kk++)
            if (kb + kk <= NHALF) zrow[kb + kk] = acc[kk];
    }
    #pragma unroll
    for (int kk = 0; kk < 4; kk++) {
        int k = kb + kk;
        if (k >= 1 && k <= NHALF - 1) zrow[N3 - k] = accs[kk];
    }
}

// ---------------- launcher ----------------------------------------------------
extern "C" void kernel_launch(void* const* d_in, const int* in_sizes, int n_in,
                              void* d_out, int out_size) {
    (void)in_sizes; (void)n_in; (void)out_size;
    static float2* bufB = nullptr;
    static float*  xh   = nullptr;
    static float*  z    = nullptr;
    static cudaStream_t s2 = nullptr;
    static cudaEvent_t  evFork = nullptr, evY = nullptr;
    if (!bufB) {   // first (uncaptured correctness) call only
        cudaGetSymbolAddress((void**)&bufB, g_bufB);
        cudaGetSymbolAddress((void**)&xh,   g_Xh);
        cudaGetSymbolAddress((void**)&z,    g_Z);
        cudaFuncSetAttribute(mix3, cudaFuncAttributeMaxDynamicSharedMemorySize,
                             (128 * MPIT * 2 + 256 * MPIT * 2) * (int)sizeof(float));
        cudaFuncSetAttribute(ykernel23, cudaFuncAttributeMaxDynamicSharedMemorySize,
                             (6912 + 12 * 49) * (int)sizeof(float2));
        cudaStreamCreateWithFlags(&s2, cudaStreamNonBlocking);
        cudaEventCreateWithFlags(&evFork, cudaEventDisableTiming);
        cudaEventCreateWithFlags(&evY,    cudaEventDisableTiming);
    }
    const float* x  = (const float*)d_in[0];   // [8,16,48,48,48]
    const float* wt = (const float*)d_in[2];   // [16,16,12,12,12]
    float* out = (float*)d_out;

    const int mix_smem = (128 * MPIT * 2 + 256 * MPIT * 2) * (int)sizeof(float);
    const int mix_grid = NHALF / MK + 1;
    const int y_smem   = (6912 + 12 * 49) * (int)sizeof(float2);

    init_tw<<<(L * L + 255) / 256, 256>>>();

    // fork: Y path on side stream, overlapped with forward X passes
    cudaEventRecord(evFork, 0);
    cudaStreamWaitEvent(s2, evFork, 0);
    ykernel1<<<(CF * 12 * 12 * L + 255) / 256, 256, 0, s2>>>(wt);
    ykernel23<<<CF * 4, 256, y_smem, s2>>>();
    cudaEventRecord(evY, s2);

    // forward: x -> Xh (main stream)
    pass_wh<<<BF * L, 256>>>(x, bufB);
    pass_d <<<BF * L, 256>>>(bufB, xh, 1.f);

    // join: mix needs Yh
    cudaStreamWaitEvent(0, evY, 0);
    mix3<<<mix_grid, 256, mix_smem>>>();

    // inverse: Z -> out (scaled 1/N3)
    pass_wh<<<BF * L, 256>>>(z, bufB);
    pass_d <<<BF * L, 256>>>(bufB, out, 1.f / (float)N3);
}

// round 13
// speedup vs baseline: 1.1426x; 1.0836x over previous
#include <cuda_runtime.h>
#include <math.h>

#define L    48
#define LH   26                 // kept frequencies (Hermitian half: 0..25)
#define N3   110592             // 48^3
#define NHALF 55296             // N3/2
#define BF   128                // B*CIN  fields for x / Z
#define CF   256                // CIN*COUT fields for Y
#define PLH  59904              // 48*48*26

// ---------------- scratch (static device memory) ---------------------------
__device__ float2 g_tw[L * L];
__device__ float2 g_tw1[L];
__device__ float2 g_emp[L];
__device__ float2 g_bufB[BF * PLH];            // 61 MB intermediate
__device__ float  g_Xh[BF * N3];
__device__ float  g_Yh[CF * N3];
__device__ float  g_Z [BF * N3];
__device__ float2 g_T1[CF * 12 * 12 * L];

// ---------------- twiddle init ---------------------------------------------
__global__ void init_tw() {
    int idx = blockIdx.x * blockDim.x + threadIdx.x;
    if (idx < L * L) {
        int k = idx / L, n = idx % L;
        int m = (k * n) % L;
        double a = -6.283185307179586476925286766559 * (double)m / (double)L;
        g_tw[idx] = make_float2((float)cos(a), (float)sin(a));
    }
    if (idx < L) {
        double a = -6.283185307179586476925286766559 * (double)idx / (double)L;
        float cx = (float)cos(a), cy = (float)sin(a);
        g_tw1[idx] = make_float2(cx, cy);
        g_emp[idx] = make_float2(cx - cy, cx + cy);
    }
}

// ============ fused pass W+H: real plane -> half spectrum [k_h][k_w] ========
// 4 barriers; stage-1 uses real-input Hermitian symmetry (k1<=4 computed).
__global__ __launch_bounds__(256, 5) void pass_wh(
    const float* __restrict__ in, float2* __restrict__ out)
{
    __shared__ __align__(16) char ubuf[48 * 27 * sizeof(float2)];  // P / C overlay
    float  (*P)[50] = reinterpret_cast<float  (*)[50]>(ubuf);      // P[w][h]
    float2 (*C)[27] = reinterpret_cast<float2 (*)[27]>(ubuf);      // C[m_h][k_w]
    __shared__ float2 A2[L][L + 1];
    __shared__ float2 B2s[LH][L + 1];                              // separate now
    __shared__ float2 TWs[L];

    int t = threadIdx.x;
    int f = blockIdx.x / L, d = blockIdx.x % L;
    const float* src = in + (size_t)f * N3 + (size_t)d * 2304;

    if (t < L) TWs[t] = g_tw1[t];
    for (int idx = t; idx < L * L; idx += 256)
        P[idx % L][idx / L] = src[idx];          // transpose: P[w][h]
    __syncthreads();                             // (1)

    float2 W8[8];
    #pragma unroll
    for (int u = 0; u < 8; u++) W8[u] = TWs[6 * u];

    int tx = t & 15, ty = t >> 4;
    int k1r = ty & 7;
    bool g1 = (tx < 10);
    int txg = g1 ? (tx + 16) : 0;

    // ---- stage 1 (w, real radix-8, Hermitian): compute k1=0..4, mirror 5..7
    for (int u = t; u < 6 * 48; u += 256) {
        int n2 = u / 48, j = u - n2 * 48;
        float ar[5] = {0,0,0,0,0}, ai[5] = {0,0,0,0,0};
        #pragma unroll
        for (int n1 = 0; n1 < 8; n1++) {
            float p = P[6 * n1 + n2][j];
            #pragma unroll
            for (int k1 = 0; k1 < 5; k1++) {
                float2 w = W8[(n1 * k1) & 7];
                ar[k1] += p * w.x;  ai[k1] += p * w.y;
            }
        }
        #pragma unroll
        for (int k1 = 0; k1 < 5; k1++)
            A2[n2 * 8 + k1][j] = make_float2(ar[k1], ai[k1]);
        #pragma unroll
        for (int k1 = 5; k1 < 8; k1++)
            A2[n2 * 8 + k1][j] = make_float2(ar[8 - k1], -ai[8 - k1]);
    }
    __syncthreads();                             // (2) — also fences last P reads

    // ---- stage 2 (w, radix-6): k_w = tx+16c (<26), h = ty+16a ---------------
    {
        float xr[3][2] = {{0.f}}, xi[3][2] = {{0.f}};
        int r8 = tx & 7;
        int i0 = 0, i1 = 0;
        int k3a = tx, k3b = tx + 16;
        #pragma unroll
        for (int n2 = 0; n2 < 6; n2++) {
            int arow = n2 * 8 + r8;
            float2 w0 = TWs[i0], w1 = TWs[i1];
            i0 += k3a; if (i0 >= L) i0 -= L;
            i1 += k3b; if (i1 >= L) i1 -= L;
            #pragma unroll
            for (int a = 0; a < 3; a++) {
                float2 v = A2[arow][ty + 16 * a];
                xr[a][0] += v.x * w0.x - v.y * w0.y;
                xi[a][0] += v.x * w0.y + v.y * w0.x;
                xr[a][1] += v.x * w1.x - v.y * w1.y;
                xi[a][1] += v.x * w1.y + v.y * w1.x;
            }
        }
        #pragma unroll
        for (int a = 0; a < 3; a++) {
            int h = ty + 16 * a;
            B2s[k3a][h] = make_float2(xr[a][0], xi[a][0]);
            if (g1) B2s[k3b][h] = make_float2(xr[a][1], xi[a][1]);
        }
    }
    __syncthreads();                             // (3)

    // ---- stage 3 (h, complex radix-8): C[n2*8+k1][k_w] (C overlays dead P) --
    {
        bool act = (t < 6 * 26);
        if (act) {
            int n2 = t / 26, kw = t - n2 * 26;
            float cr[8] = {0,0,0,0,0,0,0,0}, ci[8] = {0,0,0,0,0,0,0,0};
            #pragma unroll
            for (int n1 = 0; n1 < 8; n1++) {
                float2 q = B2s[kw][6 * n1 + n2];
                #pragma unroll
                for (int k1 = 0; k1 < 8; k1++) {
                    float2 w = W8[(n1 * k1) & 7];
                    cr[k1] += q.x * w.x - q.y * w.y;
                    ci[k1] += q.x * w.y + q.y * w.x;
                }
            }
            #pragma unroll
            for (int k1 = 0; k1 < 8; k1++)
                C[n2 * 8 + k1][kw] = make_float2(cr[k1], ci[k1]);
        }
    }
    __syncthreads();                             // (4)

    // ---- stage 4 (h, radix-6): out[k_h][k_w] --------------------------------
    {
        float xr[3][2] = {{0.f}}, xi[3][2] = {{0.f}};
        int iw[3] = {0, 0, 0};
        #pragma unroll
        for (int n2 = 0; n2 < 6; n2++) {
            int arow = n2 * 8 + k1r;
            float2 v0 = C[arow][tx];
            float2 v1 = C[arow][txg];
            #pragma unroll
            for (int a = 0; a < 3; a++) {
                float2 w = TWs[iw[a]];
                iw[a] += ty + 16 * a; if (iw[a] >= L) iw[a] -= L;
                xr[a][0] += v0.x * w.x - v0.y * w.y;
                xi[a][0] += v0.x * w.y + v0.y * w.x;
                xr[a][1] += v1.x * w.x - v1.y * w.y;
                xi[a][1] += v1.x * w.y + v1.y * w.x;
            }
        }
        float2* dst = out + (size_t)(f * L + d) * (L * LH);
        #pragma unroll
        for (int a = 0; a < 3; a++) {
            int k2 = ty + 16 * a;
            dst[(size_t)k2 * LH + tx] = make_float2(xr[a][0], xi[a][0]);
            if (g1) dst[(size_t)k2 * LH + tx + 16] = make_float2(xr[a][1], xi[a][1]);
        }
    }
}

// ============ pass D: complex, DFT along d, fold + Hermitian mirror write ===
__global__ __launch_bounds__(256, 5) void pass_d(
    const float2* __restrict__ in, float* __restrict__ out, float scale)
{
    __shared__ float2 Q2[L][LH + 1];
    __shared__ float2 A2[L][LH + 1];
    __shared__ float2 TWs[L];
    int t = threadIdx.x;
    int f = blockIdx.x / L, k2 = blockIdx.x % L;
    const float2* src = in + ((size_t)f * (L * L) + k2) * LH;

    if (t < L) TWs[t] = g_tw1[t];
    for (int idx = t; idx < L * LH; idx += 256)
        Q2[idx / LH][idx % LH] = src[(size_t)(idx / LH) * (L * LH) + (idx % LH)];
    __syncthreads();

    float2 W8[8];
    #pragma unroll
    for (int u = 0; u < 8; u++) W8[u] = TWs[6 * u];

    int tx = t & 15, ty = t >> 4;
    bool g1 = (tx < 10);
    int txg = g1 ? (tx + 16) : 0;

    if (t < 6 * 26) {
        int n2 = t / 26, kw = t - n2 * 26;
        float cr[8] = {0,0,0,0,0,0,0,0}, ci[8] = {0,0,0,0,0,0,0,0};
        #pragma unroll
        for (int n1 = 0; n1 < 8; n1++) {
            float2 q = Q2[6 * n1 + n2][kw];
            #pragma unroll
            for (int k1 = 0; k1 < 8; k1++) {
                float2 w = W8[(n1 * k1) & 7];
                cr[k1] += q.x * w.x - q.y * w.y;
                ci[k1] += q.x * w.y + q.y * w.x;
            }
        }
        #pragma unroll
        for (int k1 = 0; k1 < 8; k1++)
            A2[n2 * 8 + k1][kw] = make_float2(cr[k1], ci[k1]);
    }
    __syncthreads();

    {
        int r8 = ty & 7;
        float xr[3][2] = {{0.f}}, xi[3][2] = {{0.f}};
        int iw[3] = {0, 0, 0};
        #pragma unroll
        for (int n2 = 0; n2 < 6; n2++) {
            int arow = n2 * 8 + r8;
            float2 v0 = A2[arow][tx];
            float2 v1 = A2[arow][txg];
            #pragma unroll
            for (int a = 0; a < 3; a++) {
                float2 w = TWs[iw[a]];
                iw[a] += ty + 16 * a; if (iw[a] >= L) iw[a] -= L;
                xr[a][0] += v0.x * w.x - v0.y * w.y;
                xi[a][0] += v0.x * w.y + v0.y * w.x;
                xr[a][1] += v1.x * w.x - v1.y * w.y;
                xi[a][1] += v1.x * w.y + v1.y * w.x;
            }
        }
        int mk2 = (k2 == 0) ? 0 : L - k2;
        float* dstD = out + (size_t)f * N3 + (size_t)k2 * L;
        float* dstM = out + (size_t)f * N3 + (size_t)mk2 * L;
        int k3a = tx, k3b = tx + 16;
        int m3a = (k3a == 0) ? 0 : L - k3a;
        int m3b = L - k3b;
        #pragma unroll
        for (int a = 0; a < 3; a++) {
            int k1 = ty + 16 * a;
            int mk1 = (k1 == 0) ? 0 : L - k1;
            dstD[(size_t)k1 * 2304 + k3a]  = scale * (xr[a][0] - xi[a][0]);
            dstM[(size_t)mk1 * 2304 + m3a] = scale * (xr[a][0] + xi[a][0]);
            if (g1) {
                dstD[(size_t)k1 * 2304 + k3b]  = scale * (xr[a][1] - xi[a][1]);
                dstM[(size_t)mk1 * 2304 + m3b] = scale * (xr[a][1] + xi[a][1]);
            }
        }
    }
}

// ---------------- Y path -----------------------------------------------------
__global__ void ykernel1(const float* __restrict__ w) {
    int idx = blockIdx.x * blockDim.x + threadIdx.x;
    if (idx >= CF * 12 * 12 * L) return;
    int k3 = idx % L;
    int r  = idx / L;
    const float* wp = w + r * 12;
    float ar = 0.f, ai = 0.f;
    #pragma unroll
    for (int n3 = 0; n3 < 12; n3++) {
        float2 e = g_tw[k3 * L + n3];
        float  v = wp[n3];
        ar += v * e.x;  ai += v * e.y;
    }
    g_T1[idx] = make_float2(ar, ai);
}

__global__ __launch_bounds__(256) void ykernel23() {
    extern __shared__ float2 ysm[];
    float2* T1s = ysm;                      // 6912 float2
    float2* T2c = ysm + 6912;               // [n1*49 + k3]
    __shared__ float2 TWs[L];
    __shared__ float2 EMPs[L];

    int t  = threadIdx.x;
    int io = blockIdx.x >> 2;
    int kt = blockIdx.x & 3;

    if (t < L) { TWs[t] = g_tw1[t]; EMPs[t] = g_emp[t]; }
    const float2* src = g_T1 + (size_t)io * 6912;
    for (int idx = t; idx < 6912; idx += 256) T1s[idx] = src[idx];
    __syncthreads();

    int tx = t & 15, ty = t >> 4;

    for (int kk = 0; kk < 12; kk++) {
        int k2 = kt * 12 + kk;

        for (int idx = t; idx < 576; idx += 256) {
            int n1 = idx / 48, k3 = idx - n1 * 48;
            const float2* tp = T1s + n1 * 576 + k3;
            float ar = 0.f, ai = 0.f;
            int iw = 0;
            #pragma unroll
            for (int n2 = 0; n2 < 12; n2++) {
                float2 v = tp[n2 * 48];
                float2 e = TWs[iw];
                iw += k2; if (iw >= L) iw -= L;
                ar += v.x * e.x - v.y * e.y;
                ai += v.x * e.y + v.y * e.x;
            }
            T2c[n1 * 49 + k3] = make_float2(ar, ai);
        }
        __syncthreads();

        {
            float acc[3][3] = {{0.f}};
            int iw2[3] = {0, 0, 0};
            #pragma unroll
            for (int n1 = 0; n1 < 12; n1++) {
                float2 tv[3];
                #pragma unroll
                for (int b = 0; b < 3; b++) tv[b] = T2c[n1 * 49 + tx + 16 * b];
                #pragma unroll
                for (int a = 0; a < 3; a++) {
                    float2 e = EMPs[iw2[a]];
                    iw2[a] += ty + 16 * a; if (iw2[a] >= L) iw2[a] -= L;
                    #pragma unroll
                    for (int b = 0; b < 3; b++)
                        acc[a][b] += tv[b].x * e.x - tv[b].y * e.y;
                }
            }
            #pragma unroll
            for (int a = 0; a < 3; a++)
                #pragma unroll
                for (int b = 0; b < 3; b++)
                    g_Yh[(size_t)io * N3 + (size_t)(ty + 16 * a) * 2304
                         + (size_t)k2 * 48 + tx + 16 * b] = acc[a][b];
        }
        __syncthreads();
    }
}

// ---------------- mix4: 2b x 2o x 2k register tile, MK=16 --------------------
#define MK    16
#define MPIT  18
__global__ __launch_bounds__(256) void mix4() {
    extern __shared__ float sm[];
    float* Xa = sm;                        // [128][MPIT]
    float* Xb = Xa + 128 * MPIT;
    float* Ya = Xb + 128 * MPIT;           // [256][MPIT]
    float* Yb = Ya + 256 * MPIT;

    int t  = threadIdx.x;
    int k0 = blockIdx.x * MK;

    for (int q = t; q < 128 * MK; q += 256) {
        int kk = q & 15, bi = q >> 4;
        int k = k0 + kk; if (k > NHALF) k = NHALF;
        int sk = (k == 0) ? 0 : (N3 - k);
        Xa[bi * MPIT + kk] = g_Xh[(size_t)bi * N3 + k];
        Xb[bi * MPIT + kk] = g_Xh[(size_t)bi * N3 + sk];
    }
    for (int q = t; q < 256 * MK; q += 256) {
        int kk = q & 15, io = q >> 4;
        int k = k0 + kk; if (k > NHALF) k = NHALF;
        int sk = (k == 0) ? 0 : (N3 - k);
        Ya[io * MPIT + kk] = g_Yh[(size_t)io * N3 + k];
        Yb[io * MPIT + kk] = g_Yh[(size_t)io * N3 + sk];
    }
    __syncthreads();

    int ko = t & 7;            // k-pair: kk = 2*ko + {0,1}
    int b0 = ((t >> 3) & 3) * 2;
    int o0 = (t >> 5) * 2;

    float acc[2][2][2] = {{{0.f}}}, accs[2][2][2] = {{{0.f}}};
    #pragma unroll 4
    for (int i = 0; i < 16; i++) {
        float2 xk[2], xs[2], ya[2], yb[2];
        #pragma unroll
        for (int bb = 0; bb < 2; bb++) {
            int row = (b0 + bb) * 16 + i;
            xk[bb] = *(const float2*)&Xa[row * MPIT + 2 * ko];
            xs[bb] = *(const float2*)&Xb[row * MPIT + 2 * ko];
        }
        #pragma unroll
        for (int oo = 0; oo < 2; oo++) {
            int row = i * 16 + o0 + oo;
            ya[oo] = *(const float2*)&Ya[row * MPIT + 2 * ko];
            yb[oo] = *(const float2*)&Yb[row * MPIT + 2 * ko];
        }
        #pragma unroll
        for (int bb = 0; bb < 2; bb++) {
            float xe0 = 0.5f * (xk[bb].x + xs[bb].x);
            float xo0 = 0.5f * (xk[bb].x - xs[bb].x);
            float xe1 = 0.5f * (xk[bb].y + xs[bb].y);
            float xo1 = 0.5f * (xk[bb].y - xs[bb].y);
            #pragma unroll
            for (int oo = 0; oo < 2; oo++) {
                acc [bb][oo][0] += xe0 * ya[oo].x + xo0 * yb[oo].x;
                accs[bb][oo][0] += xe0 * yb[oo].x - xo0 * ya[oo].x;
                acc [bb][oo][1] += xe1 * ya[oo].y + xo1 * yb[oo].y;
                accs[bb][oo][1] += xe1 * yb[oo].y - xo1 * ya[oo].y;
            }
        }
    }

    #pragma unroll
    for (int bb = 0; bb < 2; bb++)
        #pragma unroll
        for (int oo = 0; oo < 2; oo++) {
            float* zrow = g_Z + (size_t)((b0 + bb) * 16 + o0 + oo) * N3;
            #pragma unroll
            for (int kk = 0; kk < 2; kk++) {
                int k = k0 + 2 * ko + kk;
                if (k <= NHALF)              zrow[k]      = acc [bb][oo][kk];
                if (k >= 1 && k <= NHALF-1)  zrow[N3 - k] = accs[bb][oo][kk];
            }
        }
}

// ---------------- launcher ----------------------------------------------------
extern "C" void kernel_launch(void* const* d_in, const int* in_sizes, int n_in,
                              void* d_out, int out_size) {
    (void)in_sizes; (void)n_in; (void)out_size;
    static float2* bufB = nullptr;
    static float*  xh   = nullptr;
    static float*  z    = nullptr;
    static cudaStream_t s2 = nullptr;
    static cudaEvent_t  evFork = nullptr, evY = nullptr;
    if (!bufB) {   // first (uncaptured correctness) call only
        cudaGetSymbolAddress((void**)&bufB, g_bufB);
        cudaGetSymbolAddress((void**)&xh,   g_Xh);
        cudaGetSymbolAddress((void**)&z,    g_Z);
        cudaFuncSetAttribute(mix4, cudaFuncAttributeMaxDynamicSharedMemorySize,
                             (128 * MPIT * 2 + 256 * MPIT * 2) * (int)sizeof(float));
        cudaFuncSetAttribute(ykernel23, cudaFuncAttributeMaxDynamicSharedMemorySize,
                             (6912 + 12 * 49) * (int)sizeof(float2));
        cudaStreamCreateWithFlags(&s2, cudaStreamNonBlocking);
        cudaEventCreateWithFlags(&evFork, cudaEventDisableTiming);
        cudaEventCreateWithFlags(&evY,    cudaEventDisableTiming);
    }
    const float* x  = (const float*)d_in[0];   // [8,16,48,48,48]
    const float* wt = (const float*)d_in[2];   // [16,16,12,12,12]
    float* out = (float*)d_out;

    const int mix_smem = (128 * MPIT * 2 + 256 * MPIT * 2) * (int)sizeof(float);
    const int mix_grid = NHALF / MK + 1;       // 3457
    const int y_smem   = (6912 + 12 * 49) * (int)sizeof(float2);

    init_tw<<<(L * L + 255) / 256, 256>>>();

    // fork: Y path on side stream, overlapped with forward X passes
    cudaEventRecord(evFork, 0);
    cudaStreamWaitEvent(s2, evFork, 0);
    ykernel1<<<(CF * 12 * 12 * L + 255) / 256, 256, 0, s2>>>(wt);
    ykernel23<<<CF * 4, 256, y_smem, s2>>>();
    cudaEventRecord(evY, s2);

    // forward: x -> Xh (main stream)
    pass_wh<<<BF * L, 256>>>(x, bufB);
    pass_d <<<BF * L, 256>>>(bufB, xh, 1.f);

    // join: mix needs Yh
    cudaStreamWaitEvent(0, evY, 0);
    mix4<<<mix_grid, 256, mix_smem>>>();

    // inverse: Z -> out (scaled 1/N3)
    pass_wh<<<BF * L, 256>>>(z, bufB);
    pass_d <<<BF * L, 256>>>(bufB, out, 1.f / (float)N3);
}

// round 14
// speedup vs baseline: 1.1659x; 1.0204x over previous
#include <cuda_runtime.h>
#include <math.h>

#define L    48
#define LH   26                 // kept frequencies (Hermitian half: 0..25)
#define N3   110592             // 48^3
#define NHALF 55296             // N3/2
#define BF   128                // B*CIN  fields for x / Z
#define CF   256                // CIN*COUT fields for Y
#define PLH  59904              // 48*48*26
#define SQ2H 0.70710678118654752440f

// ---------------- scratch (static device memory) ---------------------------
__device__ float2 g_tw[L * L];
__device__ float2 g_tw1[L];
__device__ float2 g_emp[L];
__device__ float2 g_bufB[BF * PLH];            // 61 MB intermediate
__device__ float  g_Xh[BF * N3];
__device__ float  g_Yh[CF * N3];
__device__ float  g_Z [BF * N3];
__device__ float2 g_T1[CF * 12 * 12 * L];

// ---------------- twiddle init ---------------------------------------------
__global__ void init_tw() {
    int idx = blockIdx.x * blockDim.x + threadIdx.x;
    if (idx < L * L) {
        int k = idx / L, n = idx % L;
        int m = (k * n) % L;
        double a = -6.283185307179586476925286766559 * (double)m / (double)L;
        g_tw[idx] = make_float2((float)cos(a), (float)sin(a));
    }
    if (idx < L) {
        double a = -6.283185307179586476925286766559 * (double)idx / (double)L;
        float cx = (float)cos(a), cy = (float)sin(a);
        g_tw1[idx] = make_float2(cx, cy);
        g_emp[idx] = make_float2(cx - cy, cx + cy);
    }
}

// ---------------- 8-point FFT butterfly (W8 = e^{-2pi i/8}) -----------------
__device__ __forceinline__ void fft8c(const float2 q[8], float2 X[8]) {
    float t0r=q[0].x+q[4].x, t0i=q[0].y+q[4].y;
    float t1r=q[0].x-q[4].x, t1i=q[0].y-q[4].y;
    float t2r=q[2].x+q[6].x, t2i=q[2].y+q[6].y;
    float t3r=q[2].x-q[6].x, t3i=q[2].y-q[6].y;
    float E0r=t0r+t2r, E0i=t0i+t2i;
    float E2r=t0r-t2r, E2i=t0i-t2i;
    float E1r=t1r+t3i, E1i=t1i-t3r;
    float E3r=t1r-t3i, E3i=t1i+t3r;
    float u0r=q[1].x+q[5].x, u0i=q[1].y+q[5].y;
    float u1r=q[1].x-q[5].x, u1i=q[1].y-q[5].y;
    float u2r=q[3].x+q[7].x, u2i=q[3].y+q[7].y;
    float u3r=q[3].x-q[7].x, u3i=q[3].y-q[7].y;
    float O0r=u0r+u2r, O0i=u0i+u2i;
    float O2r=u0r-u2r, O2i=u0i-u2i;
    float O1r=u1r+u3i, O1i=u1i-u3r;
    float O3r=u1r-u3i, O3i=u1i+u3r;
    float W1r=SQ2H*(O1r+O1i), W1i=SQ2H*(O1i-O1r);
    float W2r=O2i,            W2i=-O2r;
    float W3r=SQ2H*(O3i-O3r), W3i=-SQ2H*(O3r+O3i);
    X[0]=make_float2(E0r+O0r, E0i+O0i);  X[4]=make_float2(E0r-O0r, E0i-O0i);
    X[1]=make_float2(E1r+W1r, E1i+W1i);  X[5]=make_float2(E1r-W1r, E1i-W1i);
    X[2]=make_float2(E2r+W2r, E2i+W2i);  X[6]=make_float2(E2r-W2r, E2i-W2i);
    X[3]=make_float2(E3r+W3r, E3i+W3i);  X[7]=make_float2(E3r-W3r, E3i-W3i);
}

// ============ fused pass W+H: real plane -> half spectrum [k_h][k_w] ========
__global__ __launch_bounds__(256, 5) void pass_wh(
    const float* __restrict__ in, float2* __restrict__ out)
{
    __shared__ __align__(16) char ubuf[48 * 27 * sizeof(float2)];  // P / C overlay
    float  (*P)[50] = reinterpret_cast<float  (*)[50]>(ubuf);      // P[w][h]
    float2 (*C)[27] = reinterpret_cast<float2 (*)[27]>(ubuf);      // C[m_h][k_w]
    __shared__ float2 A2[L][L + 1];
    __shared__ float2 B2s[LH][L + 1];
    __shared__ float2 TWs[L];

    int t = threadIdx.x;
    int f = blockIdx.x / L, d = blockIdx.x % L;
    const float* src = in + (size_t)f * N3 + (size_t)d * 2304;

    if (t < L) TWs[t] = g_tw1[t];
    for (int idx = t; idx < L * L; idx += 256)
        P[idx % L][idx / L] = src[idx];          // transpose: P[w][h]
    __syncthreads();                             // (1)

    int tx = t & 15, ty = t >> 4;
    int k1r = ty & 7;
    bool g1 = (tx < 10);
    int txg = g1 ? (tx + 16) : 0;

    // ---- stage 1 (w, real radix-8): RFFT8 per (n2, j) -----------------------
    for (int u = t; u < 6 * 48; u += 256) {
        int n2 = u / 48, j = u - n2 * 48;
        float p[8];
        #pragma unroll
        for (int n1 = 0; n1 < 8; n1++) p[n1] = P[6 * n1 + n2][j];
        float t0=p[0]+p[4], t1=p[0]-p[4], t2=p[2]+p[6], t3=p[2]-p[6];
        float u0=p[1]+p[5], u1=p[1]-p[5], u2=p[3]+p[7], u3=p[3]-p[7];
        float E0=t0+t2, E2=t0-t2, O0=u0+u2, O2=u0-u2;
        float sa=SQ2H*(u1-u3), sb=SQ2H*(u1+u3);
        float2* arow = &A2[n2 * 8][0];
        const int pitch = L + 1;
        arow[0 * pitch + j] = make_float2(E0 + O0, 0.f);
        arow[1 * pitch + j] = make_float2(t1 + sa, -t3 - sb);
        arow[2 * pitch + j] = make_float2(E2, -O2);
        arow[3 * pitch + j] = make_float2(t1 - sa,  t3 - sb);
        arow[4 * pitch + j] = make_float2(E0 - O0, 0.f);
        arow[5 * pitch + j] = make_float2(t1 - sa, -(t3 - sb));
        arow[6 * pitch + j] = make_float2(E2,  O2);
        arow[7 * pitch + j] = make_float2(t1 + sa,  t3 + sb);
    }
    __syncthreads();                             // (2) — also fences last P reads

    // ---- stage 2 (w, radix-6): k_w = tx+16c (<26), h = ty+16a ---------------
    {
        float xr[3][2] = {{0.f}}, xi[3][2] = {{0.f}};
        int r8 = tx & 7;
        int i0 = 0, i1 = 0;
        int k3a = tx, k3b = tx + 16;
        #pragma unroll
        for (int n2 = 0; n2 < 6; n2++) {
            int arow = n2 * 8 + r8;
            float2 w0 = TWs[i0], w1 = TWs[i1];
            i0 += k3a; if (i0 >= L) i0 -= L;
            i1 += k3b; if (i1 >= L) i1 -= L;
            #pragma unroll
            for (int a = 0; a < 3; a++) {
                float2 v = A2[arow][ty + 16 * a];
                xr[a][0] += v.x * w0.x - v.y * w0.y;
                xi[a][0] += v.x * w0.y + v.y * w0.x;
                xr[a][1] += v.x * w1.x - v.y * w1.y;
                xi[a][1] += v.x * w1.y + v.y * w1.x;
            }
        }
        #pragma unroll
        for (int a = 0; a < 3; a++) {
            int h = ty + 16 * a;
            B2s[k3a][h] = make_float2(xr[a][0], xi[a][0]);
            if (g1) B2s[k3b][h] = make_float2(xr[a][1], xi[a][1]);
        }
    }
    __syncthreads();                             // (3)

    // ---- stage 3 (h, complex radix-8): FFT8 per (n2, k_w), C overlays P -----
    {
        bool act = (t < 6 * 26);
        if (act) {
            int n2 = t / 26, kw = t - n2 * 26;
            float2 q[8], X[8];
            #pragma unroll
            for (int n1 = 0; n1 < 8; n1++) q[n1] = B2s[kw][6 * n1 + n2];
            fft8c(q, X);
            #pragma unroll
            for (int k1 = 0; k1 < 8; k1++)
                C[n2 * 8 + k1][kw] = X[k1];
        }
    }
    __syncthreads();                             // (4)

    // ---- stage 4 (h, radix-6): out[k_h][k_w] --------------------------------
    {
        float xr[3][2] = {{0.f}}, xi[3][2] = {{0.f}};
        int iw[3] = {0, 0, 0};
        #pragma unroll
        for (int n2 = 0; n2 < 6; n2++) {
            int arow = n2 * 8 + k1r;
            float2 v0 = C[arow][tx];
            float2 v1 = C[arow][txg];
            #pragma unroll
            for (int a = 0; a < 3; a++) {
                float2 w = TWs[iw[a]];
                iw[a] += ty + 16 * a; if (iw[a] >= L) iw[a] -= L;
                xr[a][0] += v0.x * w.x - v0.y * w.y;
                xi[a][0] += v0.x * w.y + v0.y * w.x;
                xr[a][1] += v1.x * w.x - v1.y * w.y;
                xi[a][1] += v1.x * w.y + v1.y * w.x;
            }
        }
        float2* dst = out + (size_t)(f * L + d) * (L * LH);
        #pragma unroll
        for (int a = 0; a < 3; a++) {
            int k2 = ty + 16 * a;
            dst[(size_t)k2 * LH + tx] = make_float2(xr[a][0], xi[a][0]);
            if (g1) dst[(size_t)k2 * LH + tx + 16] = make_float2(xr[a][1], xi[a][1]);
        }
    }
}

// ============ pass D: complex, DFT along d, fold + Hermitian mirror write ===
__global__ __launch_bounds__(256, 5) void pass_d(
    const float2* __restrict__ in, float* __restrict__ out, float scale)
{
    __shared__ float2 Q2[L][LH + 1];
    __shared__ float2 A2[L][LH + 1];
    __shared__ float2 TWs[L];
    int t = threadIdx.x;
    int f = blockIdx.x / L, k2 = blockIdx.x % L;
    const float2* src = in + ((size_t)f * (L * L) + k2) * LH;

    if (t < L) TWs[t] = g_tw1[t];
    for (int idx = t; idx < L * LH; idx += 256)
        Q2[idx / LH][idx % LH] = src[(size_t)(idx / LH) * (L * LH) + (idx % LH)];
    __syncthreads();

    int tx = t & 15, ty = t >> 4;
    bool g1 = (tx < 10);
    int txg = g1 ? (tx + 16) : 0;

    // ---- stage 1 (d, complex radix-8): FFT8 per (n2, k_w) -------------------
    if (t < 6 * 26) {
        int n2 = t / 26, kw = t - n2 * 26;
        float2 q[8], X[8];
        #pragma unroll
        for (int n1 = 0; n1 < 8; n1++) q[n1] = Q2[6 * n1 + n2][kw];
        fft8c(q, X);
        #pragma unroll
        for (int k1 = 0; k1 < 8; k1++)
            A2[n2 * 8 + k1][kw] = X[k1];
    }
    __syncthreads();

    // ---- stage 2 (d, radix-6) + fold/mirror ---------------------------------
    {
        int r8 = ty & 7;
        float xr[3][2] = {{0.f}}, xi[3][2] = {{0.f}};
        int iw[3] = {0, 0, 0};
        #pragma unroll
        for (int n2 = 0; n2 < 6; n2++) {
            int arow = n2 * 8 + r8;
            float2 v0 = A2[arow][tx];
            float2 v1 = A2[arow][txg];
            #pragma unroll
            for (int a = 0; a < 3; a++) {
                float2 w = TWs[iw[a]];
                iw[a] += ty + 16 * a; if (iw[a] >= L) iw[a] -= L;
                xr[a][0] += v0.x * w.x - v0.y * w.y;
                xi[a][0] += v0.x * w.y + v0.y * w.x;
                xr[a][1] += v1.x * w.x - v1.y * w.y;
                xi[a][1] += v1.x * w.y + v1.y * w.x;
            }
        }
        int mk2 = (k2 == 0) ? 0 : L - k2;
        float* dstD = out + (size_t)f * N3 + (size_t)k2 * L;
        float* dstM = out + (size_t)f * N3 + (size_t)mk2 * L;
        int k3a = tx, k3b = tx + 16;
        int m3a = (k3a == 0) ? 0 : L - k3a;
        int m3b = L - k3b;
        #pragma unroll
        for (int a = 0; a < 3; a++) {
            int k1 = ty + 16 * a;
            int mk1 = (k1 == 0) ? 0 : L - k1;
            dstD[(size_t)k1 * 2304 + k3a]  = scale * (xr[a][0] - xi[a][0]);
            dstM[(size_t)mk1 * 2304 + m3a] = scale * (xr[a][0] + xi[a][0]);
            if (g1) {
                dstD[(size_t)k1 * 2304 + k3b]  = scale * (xr[a][1] - xi[a][1]);
                dstM[(size_t)mk1 * 2304 + m3b] = scale * (xr[a][1] + xi[a][1]);
            }
        }
    }
}

// ---------------- Y path -----------------------------------------------------
__global__ void ykernel1(const float* __restrict__ w) {
    int idx = blockIdx.x * blockDim.x + threadIdx.x;
    if (idx >= CF * 12 * 12 * L) return;
    int k3 = idx % L;
    int r  = idx / L;
    const float* wp = w + r * 12;
    float ar = 0.f, ai = 0.f;
    #pragma unroll
    for (int n3 = 0; n3 < 12; n3++) {
        float2 e = g_tw[k3 * L + n3];
        float  v = wp[n3];
        ar += v * e.x;  ai += v * e.y;
    }
    g_T1[idx] = make_float2(ar, ai);
}

__global__ __launch_bounds__(256) void ykernel23() {
    extern __shared__ float2 ysm[];
    float2* T1s = ysm;                      // 6912 float2
    float2* T2c = ysm + 6912;               // [n1*49 + k3]
    __shared__ float2 TWs[L];
    __shared__ float2 EMPs[L];

    int t  = threadIdx.x;
    int io = blockIdx.x >> 2;
    int kt = blockIdx.x & 3;

    if (t < L) { TWs[t] = g_tw1[t]; EMPs[t] = g_emp[t]; }
    const float2* src = g_T1 + (size_t)io * 6912;
    for (int idx = t; idx < 6912; idx += 256) T1s[idx] = src[idx];
    __syncthreads();

    int tx = t & 15, ty = t >> 4;

    for (int kk = 0; kk < 12; kk++) {
        int k2 = kt * 12 + kk;

        for (int idx = t; idx < 576; idx += 256) {
            int n1 = idx / 48, k3 = idx - n1 * 48;
            const float2* tp = T1s + n1 * 576 + k3;
            float ar = 0.f, ai = 0.f;
            int iw = 0;
            #pragma unroll
            for (int n2 = 0; n2 < 12; n2++) {
                float2 v = tp[n2 * 48];
                float2 e = TWs[iw];
                iw += k2; if (iw >= L) iw -= L;
                ar += v.x * e.x - v.y * e.y;
                ai += v.x * e.y + v.y * e.x;
            }
            T2c[n1 * 49 + k3] = make_float2(ar, ai);
        }
        __syncthreads();

        {
            float acc[3][3] = {{0.f}};
            int iw2[3] = {0, 0, 0};
            #pragma unroll
            for (int n1 = 0; n1 < 12; n1++) {
                float2 tv[3];
                #pragma unroll
                for (int b = 0; b < 3; b++) tv[b] = T2c[n1 * 49 + tx + 16 * b];
                #pragma unroll
                for (int a = 0; a < 3; a++) {
                    float2 e = EMPs[iw2[a]];
                    iw2[a] += ty + 16 * a; if (iw2[a] >= L) iw2[a] -= L;
                    #pragma unroll
                    for (int b = 0; b < 3; b++)
                        acc[a][b] += tv[b].x * e.x - tv[b].y * e.y;
                }
            }
            #pragma unroll
            for (int a = 0; a < 3; a++)
                #pragma unroll
                for (int b = 0; b < 3; b++)
                    g_Yh[(size_t)io * N3 + (size_t)(ty + 16 * a) * 2304
                         + (size_t)k2 * 48 + tx + 16 * b] = acc[a][b];
        }
        __syncthreads();
    }
}

// ---------------- mix4: 2b x 2o x 2k register tile, MK=16 --------------------
#define MK    16
#define MPIT  18
__global__ __launch_bounds__(256) void mix4() {
    extern __shared__ float sm[];
    float* Xa = sm;                        // [128][MPIT]
    float* Xb = Xa + 128 * MPIT;
    float* Ya = Xb + 128 * MPIT;           // [256][MPIT]
    float* Yb = Ya + 256 * MPIT;

    int t  = threadIdx.x;
    int k0 = blockIdx.x * MK;

    for (int q = t; q < 128 * MK; q += 256) {
        int kk = q & 15, bi = q >> 4;
        int k = k0 + kk; if (k > NHALF) k = NHALF;
        int sk = (k == 0) ? 0 : (N3 - k);
        Xa[bi * MPIT + kk] = g_Xh[(size_t)bi * N3 + k];
        Xb[bi * MPIT + kk] = g_Xh[(size_t)bi * N3 + sk];
    }
    for (int q = t; q < 256 * MK; q += 256) {
        int kk = q & 15, io = q >> 4;
        int k = k0 + kk; if (k > NHALF) k = NHALF;
        int sk = (k == 0) ? 0 : (N3 - k);
        Ya[io * MPIT + kk] = g_Yh[(size_t)io * N3 + k];
        Yb[io * MPIT + kk] = g_Yh[(size_t)io * N3 + sk];
    }
    __syncthreads();

    int ko = t & 7;            // k-pair: kk = 2*ko + {0,1}
    int b0 = ((t >> 3) & 3) * 2;
    int o0 = (t >> 5) * 2;

    float acc[2][2][2] = {{{0.f}}}, accs[2][2][2] = {{{0.f}}};
    #pragma unroll 4
    for (int i = 0; i < 16; i++) {
        float2 xk[2], xs[2], ya[2], yb[2];
        #pragma unroll
        for (int bb = 0; bb < 2; bb++) {
            int row = (b0 + bb) * 16 + i;
            xk[bb] = *(const float2*)&Xa[row * MPIT + 2 * ko];
            xs[bb] = *(const float2*)&Xb[row * MPIT + 2 * ko];
        }
        #pragma unroll
        for (int oo = 0; oo < 2; oo++) {
            int row = i * 16 + o0 + oo;
            ya[oo] = *(const float2*)&Ya[row * MPIT + 2 * ko];
            yb[oo] = *(const float2*)&Yb[row * MPIT + 2 * ko];
        }
        #pragma unroll
        for (int bb = 0; bb < 2; bb++) {
            float xe0 = 0.5f * (xk[bb].x + xs[bb].x);
            float xo0 = 0.5f * (xk[bb].x - xs[bb].x);
            float xe1 = 0.5f * (xk[bb].y + xs[bb].y);
            float xo1 = 0.5f * (xk[bb].y - xs[bb].y);
            #pragma unroll
            for (int oo = 0; oo < 2; oo++) {
                acc [bb][oo][0] += xe0 * ya[oo].x + xo0 * yb[oo].x;
                accs[bb][oo][0] += xe0 * yb[oo].x - xo0 * ya[oo].x;
                acc [bb][oo][1] += xe1 * ya[oo].y + xo1 * yb[oo].y;
                accs[bb][oo][1] += xe1 * yb[oo].y - xo1 * ya[oo].y;
            }
        }
    }

    #pragma unroll
    for (int bb = 0; bb < 2; bb++)
        #pragma unroll
        for (int oo = 0; oo < 2; oo++) {
            float* zrow = g_Z + (size_t)((b0 + bb) * 16 + o0 + oo) * N3;
            #pragma unroll
            for (int kk = 0; kk < 2; kk++) {
                int k = k0 + 2 * ko + kk;
                if (k <= NHALF)              zrow[k]      = acc [bb][oo][kk];
                if (k >= 1 && k <= NHALF-1)  zrow[N3 - k] = accs[bb][oo][kk];
            }
        }
}

// ---------------- launcher ----------------------------------------------------
extern "C" void kernel_launch(void* const* d_in, const int* in_sizes, int n_in,
                              void* d_out, int out_size) {
    (void)in_sizes; (void)n_in; (void)out_size;
    static float2* bufB = nullptr;
    static float*  xh   = nullptr;
    static float*  z    = nullptr;
    static cudaStream_t s2 = nullptr;
    static cudaEvent_t  evFork = nullptr, evY = nullptr;
    if (!bufB) {   // first (uncaptured correctness) call only
        cudaGetSymbolAddress((void**)&bufB, g_bufB);
        cudaGetSymbolAddress((void**)&xh,   g_Xh);
        cudaGetSymbolAddress((void**)&z,    g_Z);
        cudaFuncSetAttribute(mix4, cudaFuncAttributeMaxDynamicSharedMemorySize,
                             (128 * MPIT * 2 + 256 * MPIT * 2) * (int)sizeof(float));
        cudaFuncSetAttribute(ykernel23, cudaFuncAttributeMaxDynamicSharedMemorySize,
                             (6912 + 12 * 49) * (int)sizeof(float2));
        cudaStreamCreateWithFlags(&s2, cudaStreamNonBlocking);
        cudaEventCreateWithFlags(&evFork, cudaEventDisableTiming);
        cudaEventCreateWithFlags(&evY,    cudaEventDisableTiming);
    }
    const float* x  = (const float*)d_in[0];   // [8,16,48,48,48]
    const float* wt = (const float*)d_in[2];   // [16,16,12,12,12]
    float* out = (float*)d_out;

    const int mix_smem = (128 * MPIT * 2 + 256 * MPIT * 2) * (int)sizeof(float);
    const int mix_grid = NHALF / MK + 1;       // 3457
    const int y_smem   = (6912 + 12 * 49) * (int)sizeof(float2);

    init_tw<<<(L * L + 255) / 256, 256>>>();

    // fork: Y path on side stream, overlapped with forward X passes
    cudaEventRecord(evFork, 0);
    cudaStreamWaitEvent(s2, evFork, 0);
    ykernel1<<<(CF * 12 * 12 * L + 255) / 256, 256, 0, s2>>>(wt);
    ykernel23<<<CF * 4, 256, y_smem, s2>>>();
    cudaEventRecord(evY, s2);

    // forward: x -> Xh (main stream)
    pass_wh<<<BF * L, 256>>>(x, bufB);
    pass_d <<<BF * L, 256>>>(bufB, xh, 1.f);

    // join: mix needs Yh
    cudaStreamWaitEvent(0, evY, 0);
    mix4<<<mix_grid, 256, mix_smem>>>();

    // inverse: Z -> out (scaled 1/N3)
    pass_wh<<<BF * L, 256>>>(z, bufB);
    pass_d <<<BF * L, 256>>>(bufB, out, 1.f / (float)N3);
}

// round 15
// speedup vs baseline: 1.1670x; 1.0010x over previous
#include <cuda_runtime.h>
#include <math.h>

#define L    48
#define LH   26                 // kept frequencies (Hermitian half: 0..25)
#define N3   110592             // 48^3
#define NHALF 55296             // N3/2
#define BF   128                // B*CIN  fields for x / Z
#define CF   256                // CIN*COUT fields for Y
#define PLH  59904              // 48*48*26
#define SQ2H 0.70710678118654752440f

// ---------------- scratch (static device memory) ---------------------------
__device__ float2 g_tw[L * L];
__device__ float2 g_tw1[L];
__device__ float2 g_emp[L];
__device__ float2 g_bufB[BF * PLH];            // 61 MB intermediate
__device__ float  g_Xh[BF * N3];
__device__ float  g_Yh[CF * N3];
__device__ float  g_Z [BF * N3];
__device__ float2 g_T1[CF * 12 * 12 * L];

// ---------------- twiddle init ---------------------------------------------
__global__ void init_tw() {
    int idx = blockIdx.x * blockDim.x + threadIdx.x;
    if (idx < L * L) {
        int k = idx / L, n = idx % L;
        int m = (k * n) % L;
        double a = -6.283185307179586476925286766559 * (double)m / (double)L;
        g_tw[idx] = make_float2((float)cos(a), (float)sin(a));
    }
    if (idx < L) {
        double a = -6.283185307179586476925286766559 * (double)idx / (double)L;
        float cx = (float)cos(a), cy = (float)sin(a);
        g_tw1[idx] = make_float2(cx, cy);
        g_emp[idx] = make_float2(cx - cy, cx + cy);
    }
}

// ---------------- 8-point FFT butterfly (W8 = e^{-2pi i/8}) -----------------
__device__ __forceinline__ void fft8c(const float2 q[8], float2 X[8]) {
    float t0r=q[0].x+q[4].x, t0i=q[0].y+q[4].y;
    float t1r=q[0].x-q[4].x, t1i=q[0].y-q[4].y;
    float t2r=q[2].x+q[6].x, t2i=q[2].y+q[6].y;
    float t3r=q[2].x-q[6].x, t3i=q[2].y-q[6].y;
    float E0r=t0r+t2r, E0i=t0i+t2i;
    float E2r=t0r-t2r, E2i=t0i-t2i;
    float E1r=t1r+t3i, E1i=t1i-t3r;
    float E3r=t1r-t3i, E3i=t1i+t3r;
    float u0r=q[1].x+q[5].x, u0i=q[1].y+q[5].y;
    float u1r=q[1].x-q[5].x, u1i=q[1].y-q[5].y;
    float u2r=q[3].x+q[7].x, u2i=q[3].y+q[7].y;
    float u3r=q[3].x-q[7].x, u3i=q[3].y-q[7].y;
    float O0r=u0r+u2r, O0i=u0i+u2i;
    float O2r=u0r-u2r, O2i=u0i-u2i;
    float O1r=u1r+u3i, O1i=u1i-u3r;
    float O3r=u1r-u3i, O3i=u1i+u3r;
    float W1r=SQ2H*(O1r+O1i), W1i=SQ2H*(O1i-O1r);
    float W2r=O2i,            W2i=-O2r;
    float W3r=SQ2H*(O3i-O3r), W3i=-SQ2H*(O3r+O3i);
    X[0]=make_float2(E0r+O0r, E0i+O0i);  X[4]=make_float2(E0r-O0r, E0i-O0i);
    X[1]=make_float2(E1r+W1r, E1i+W1i);  X[5]=make_float2(E1r-W1r, E1i-W1i);
    X[2]=make_float2(E2r+W2r, E2i+W2i);  X[6]=make_float2(E2r-W2r, E2i-W2i);
    X[3]=make_float2(E3r+W3r, E3i+W3i);  X[7]=make_float2(E3r-W3r, E3i-W3i);
}

// ============ fused pass W+H: real plane -> half spectrum [k_h][k_w] ========
__global__ __launch_bounds__(256, 5) void pass_wh(
    const float* __restrict__ in, float2* __restrict__ out)
{
    __shared__ __align__(16) char ubuf[48 * 28 * sizeof(float2)];  // P / C overlay
    float  (*P)[50] = reinterpret_cast<float  (*)[50]>(ubuf);      // P[w][h]
    float2 (*C)[28] = reinterpret_cast<float2 (*)[28]>(ubuf);      // C[m_h][k_w], 16B rows
    __shared__ float2 A2[L][L + 1];
    __shared__ float2 B2s[LH][L + 1];
    __shared__ float2 TWs[L];

    int t = threadIdx.x;
    int f = blockIdx.x / L, d = blockIdx.x % L;
    const float* src = in + (size_t)f * N3 + (size_t)d * 2304;

    if (t < L) TWs[t] = g_tw1[t];
    for (int idx = t; idx < L * L; idx += 256)
        P[idx % L][idx / L] = src[idx];          // transpose: P[w][h]
    __syncthreads();                             // (1)

    int tx = t & 15, ty = t >> 4;
    int k1r = ty & 7;
    bool g1 = (tx < 10);
    bool tp = (tx < 13);

    // ---- stage 1 (w, real radix-8): RFFT8 per (n2, j) -----------------------
    for (int u = t; u < 6 * 48; u += 256) {
        int n2 = u / 48, j = u - n2 * 48;
        float p[8];
        #pragma unroll
        for (int n1 = 0; n1 < 8; n1++) p[n1] = P[6 * n1 + n2][j];
        float t0=p[0]+p[4], t1=p[0]-p[4], t2=p[2]+p[6], t3=p[2]-p[6];
        float u0=p[1]+p[5], u1=p[1]-p[5], u2=p[3]+p[7], u3=p[3]-p[7];
        float E0=t0+t2, E2=t0-t2, O0=u0+u2, O2=u0-u2;
        float sa=SQ2H*(u1-u3), sb=SQ2H*(u1+u3);
        float2* arow = &A2[n2 * 8][0];
        const int pitch = L + 1;
        arow[0 * pitch + j] = make_float2(E0 + O0, 0.f);
        arow[1 * pitch + j] = make_float2(t1 + sa, -t3 - sb);
        arow[2 * pitch + j] = make_float2(E2, -O2);
        arow[3 * pitch + j] = make_float2(t1 - sa,  t3 - sb);
        arow[4 * pitch + j] = make_float2(E0 - O0, 0.f);
        arow[5 * pitch + j] = make_float2(t1 - sa, -(t3 - sb));
        arow[6 * pitch + j] = make_float2(E2,  O2);
        arow[7 * pitch + j] = make_float2(t1 + sa,  t3 + sb);
    }
    __syncthreads();                             // (2) — also fences last P reads

    // ---- stage 2 (w, radix-6): k_w = tx+16c (<26), h = ty+16a ---------------
    {
        float xr[3][2] = {{0.f}}, xi[3][2] = {{0.f}};
        int r8 = tx & 7;
        int i0 = 0, i1 = 0;
        int k3a = tx, k3b = tx + 16;
        #pragma unroll
        for (int n2 = 0; n2 < 6; n2++) {
            int arow = n2 * 8 + r8;
            float2 w0 = TWs[i0], w1 = TWs[i1];
            i0 += k3a; if (i0 >= L) i0 -= L;
            i1 += k3b; if (i1 >= L) i1 -= L;
            #pragma unroll
            for (int a = 0; a < 3; a++) {
                float2 v = A2[arow][ty + 16 * a];
                xr[a][0] += v.x * w0.x - v.y * w0.y;
                xi[a][0] += v.x * w0.y + v.y * w0.x;
                xr[a][1] += v.x * w1.x - v.y * w1.y;
                xi[a][1] += v.x * w1.y + v.y * w1.x;
            }
        }
        #pragma unroll
        for (int a = 0; a < 3; a++) {
            int h = ty + 16 * a;
            B2s[k3a][h] = make_float2(xr[a][0], xi[a][0]);
            if (g1) B2s[k3b][h] = make_float2(xr[a][1], xi[a][1]);
        }
    }
    __syncthreads();                             // (3)

    // ---- stage 3 (h, complex radix-8): FFT8 per (n2, k_w), C overlays P -----
    {
        bool act = (t < 6 * 26);
        if (act) {
            int n2 = t / 26, kw = t - n2 * 26;
            float2 q[8], X[8];
            #pragma unroll
            for (int n1 = 0; n1 < 8; n1++) q[n1] = B2s[kw][6 * n1 + n2];
            fft8c(q, X);
            #pragma unroll
            for (int k1 = 0; k1 < 8; k1++)
                C[n2 * 8 + k1][kw] = X[k1];
        }
    }
    __syncthreads();                             // (4)

    // ---- stage 4 (h, radix-6): k_w pair (2tx, 2tx+1), shared twiddle --------
    if (tp) {
        float xr[3][2] = {{0.f}}, xi[3][2] = {{0.f}};
        int iw[3] = {0, 0, 0};
        #pragma unroll
        for (int n2 = 0; n2 < 6; n2++) {
            int arow = n2 * 8 + k1r;
            float4 vv = *(const float4*)&C[arow][2 * tx];   // two float2, one LDS.128
            #pragma unroll
            for (int a = 0; a < 3; a++) {
                float2 w = TWs[iw[a]];
                iw[a] += ty + 16 * a; if (iw[a] >= L) iw[a] -= L;
                xr[a][0] += vv.x * w.x - vv.y * w.y;
                xi[a][0] += vv.x * w.y + vv.y * w.x;
                xr[a][1] += vv.z * w.x - vv.w * w.y;
                xi[a][1] += vv.z * w.y + vv.w * w.x;
            }
        }
        float2* dst = out + (size_t)(f * L + d) * (L * LH);
        #pragma unroll
        for (int a = 0; a < 3; a++) {
            int k2 = ty + 16 * a;
            float4 o4 = make_float4(xr[a][0], xi[a][0], xr[a][1], xi[a][1]);
            *(float4*)&dst[(size_t)k2 * LH + 2 * tx] = o4;
        }
    }
}

// ============ pass D: complex, DFT along d, fold + Hermitian mirror write ===
__global__ __launch_bounds__(256, 5) void pass_d(
    const float2* __restrict__ in, float* __restrict__ out, float scale)
{
    __shared__ float2 Q2[L][LH + 1];
    __shared__ __align__(16) float2 A2[L][LH + 2];   // pitch 28 -> 16B rows
    __shared__ float2 TWs[L];
    int t = threadIdx.x;
    int f = blockIdx.x / L, k2 = blockIdx.x % L;
    const float2* src = in + ((size_t)f * (L * L) + k2) * LH;

    if (t < L) TWs[t] = g_tw1[t];
    for (int idx = t; idx < L * LH; idx += 256)
        Q2[idx / LH][idx % LH] = src[(size_t)(idx / LH) * (L * LH) + (idx % LH)];
    __syncthreads();

    int tx = t & 15, ty = t >> 4;
    bool tp = (tx < 13);

    // ---- stage 1 (d, complex radix-8): FFT8 per (n2, k_w) -------------------
    if (t < 6 * 26) {
        int n2 = t / 26, kw = t - n2 * 26;
        float2 q[8], X[8];
        #pragma unroll
        for (int n1 = 0; n1 < 8; n1++) q[n1] = Q2[6 * n1 + n2][kw];
        fft8c(q, X);
        #pragma unroll
        for (int k1 = 0; k1 < 8; k1++)
            A2[n2 * 8 + k1][kw] = X[k1];
    }
    __syncthreads();

    // ---- stage 2 (d, radix-6) + fold/mirror: k_w pair (2tx, 2tx+1) ----------
    if (tp) {
        int r8 = ty & 7;
        float xr[3][2] = {{0.f}}, xi[3][2] = {{0.f}};
        int iw[3] = {0, 0, 0};
        #pragma unroll
        for (int n2 = 0; n2 < 6; n2++) {
            int arow = n2 * 8 + r8;
            float4 vv = *(const float4*)&A2[arow][2 * tx];
            #pragma unroll
            for (int a = 0; a < 3; a++) {
                float2 w = TWs[iw[a]];
                iw[a] += ty + 16 * a; if (iw[a] >= L) iw[a] -= L;
                xr[a][0] += vv.x * w.x - vv.y * w.y;
                xi[a][0] += vv.x * w.y + vv.y * w.x;
                xr[a][1] += vv.z * w.x - vv.w * w.y;
                xi[a][1] += vv.z * w.y + vv.w * w.x;
            }
        }
        int mk2 = (k2 == 0) ? 0 : L - k2;
        float* dstD = out + (size_t)f * N3 + (size_t)k2 * L;
        float* dstM = out + (size_t)f * N3 + (size_t)mk2 * L;
        #pragma unroll
        for (int a = 0; a < 3; a++) {
            int k1 = ty + 16 * a;
            int mk1 = (k1 == 0) ? 0 : L - k1;
            float D0 = scale * (xr[a][0] - xi[a][0]);
            float D1 = scale * (xr[a][1] - xi[a][1]);
            float M0 = scale * (xr[a][0] + xi[a][0]);
            float M1 = scale * (xr[a][1] + xi[a][1]);
            *(float2*)&dstD[(size_t)k1 * 2304 + 2 * tx] = make_float2(D0, D1);
            if (tx == 0) {
                dstM[(size_t)mk1 * 2304 + 0]  = M0;
                dstM[(size_t)mk1 * 2304 + 47] = M1;
            } else {
                dstM[(size_t)mk1 * 2304 + 48 - 2 * tx] = M0;
                dstM[(size_t)mk1 * 2304 + 47 - 2 * tx] = M1;
            }
        }
    }
}

// ---------------- Y path -----------------------------------------------------
__global__ void ykernel1(const float* __restrict__ w) {
    int idx = blockIdx.x * blockDim.x + threadIdx.x;
    if (idx >= CF * 12 * 12 * L) return;
    int k3 = idx % L;
    int r  = idx / L;
    const float* wp = w + r * 12;
    float ar = 0.f, ai = 0.f;
    #pragma unroll
    for (int n3 = 0; n3 < 12; n3++) {
        float2 e = g_tw[k3 * L + n3];
        float  v = wp[n3];
        ar += v * e.x;  ai += v * e.y;
    }
    g_T1[idx] = make_float2(ar, ai);
}

__global__ __launch_bounds__(256) void ykernel23() {
    extern __shared__ float2 ysm[];
    float2* T1s = ysm;                      // 6912 float2
    float2* T2c = ysm + 6912;               // [n1*49 + k3]
    __shared__ float2 TWs[L];
    __shared__ float2 EMPs[L];

    int t  = threadIdx.x;
    int io = blockIdx.x >> 2;
    int kt = blockIdx.x & 3;

    if (t < L) { TWs[t] = g_tw1[t]; EMPs[t] = g_emp[t]; }
    const float2* src = g_T1 + (size_t)io * 6912;
    for (int idx = t; idx < 6912; idx += 256) T1s[idx] = src[idx];
    __syncthreads();

    int tx = t & 15, ty = t >> 4;

    for (int kk = 0; kk < 12; kk++) {
        int k2 = kt * 12 + kk;

        for (int idx = t; idx < 576; idx += 256) {
            int n1 = idx / 48, k3 = idx - n1 * 48;
            const float2* tp2 = T1s + n1 * 576 + k3;
            float ar = 0.f, ai = 0.f;
            int iw = 0;
            #pragma unroll
            for (int n2 = 0; n2 < 12; n2++) {
                float2 v = tp2[n2 * 48];
                float2 e = TWs[iw];
                iw += k2; if (iw >= L) iw -= L;
                ar += v.x * e.x - v.y * e.y;
                ai += v.x * e.y + v.y * e.x;
            }
            T2c[n1 * 49 + k3] = make_float2(ar, ai);
        }
        __syncthreads();

        {
            float acc[3][3] = {{0.f}};
            int iw2[3] = {0, 0, 0};
            #pragma unroll
            for (int n1 = 0; n1 < 12; n1++) {
                float2 tv[3];
                #pragma unroll
                for (int b = 0; b < 3; b++) tv[b] = T2c[n1 * 49 + tx + 16 * b];
                #pragma unroll
                for (int a = 0; a < 3; a++) {
                    float2 e = EMPs[iw2[a]];
                    iw2[a] += ty + 16 * a; if (iw2[a] >= L) iw2[a] -= L;
                    #pragma unroll
                    for (int b = 0; b < 3; b++)
                        acc[a][b] += tv[b].x * e.x - tv[b].y * e.y;
                }
            }
            #pragma unroll
            for (int a = 0; a < 3; a++)
                #pragma unroll
                for (int b = 0; b < 3; b++)
                    g_Yh[(size_t)io * N3 + (size_t)(ty + 16 * a) * 2304
                         + (size_t)k2 * 48 + tx + 16 * b] = acc[a][b];
        }
        __syncthreads();
    }
}

// ---------------- mix4: 2b x 2o x 2k register tile, MK=16 --------------------
#define MK    16
#define MPIT  18
__global__ __launch_bounds__(256) void mix4() {
    extern __shared__ float sm[];
    float* Xa = sm;                        // [128][MPIT]
    float* Xb = Xa + 128 * MPIT;
    float* Ya = Xb + 128 * MPIT;           // [256][MPIT]
    float* Yb = Ya + 256 * MPIT;

    int t  = threadIdx.x;
    int k0 = blockIdx.x * MK;

    for (int q = t; q < 128 * MK; q += 256) {
        int kk = q & 15, bi = q >> 4;
        int k = k0 + kk; if (k > NHALF) k = NHALF;
        int sk = (k == 0) ? 0 : (N3 - k);
        Xa[bi * MPIT + kk] = g_Xh[(size_t)bi * N3 + k];
        Xb[bi * MPIT + kk] = g_Xh[(size_t)bi * N3 + sk];
    }
    for (int q = t; q < 256 * MK; q += 256) {
        int kk = q & 15, io = q >> 4;
        int k = k0 + kk; if (k > NHALF) k = NHALF;
        int sk = (k == 0) ? 0 : (N3 - k);
        Ya[io * MPIT + kk] = g_Yh[(size_t)io * N3 + k];
        Yb[io * MPIT + kk] = g_Yh[(size_t)io * N3 + sk];
    }
    __syncthreads();

    int ko = t & 7;            // k-pair: kk = 2*ko + {0,1}
    int b0 = ((t >> 3) & 3) * 2;
    int o0 = (t >> 5) * 2;

    float acc[2][2][2] = {{{0.f}}}, accs[2][2][2] = {{{0.f}}};
    #pragma unroll 4
    for (int i = 0; i < 16; i++) {
        float2 xk[2], xs[2], ya[2], yb[2];
        #pragma unroll
        for (int bb = 0; bb < 2; bb++) {
            int row = (b0 + bb) * 16 + i;
            xk[bb] = *(const float2*)&Xa[row * MPIT + 2 * ko];
            xs[bb] = *(const float2*)&Xb[row * MPIT + 2 * ko];
        }
        #pragma unroll
        for (int oo = 0; oo < 2; oo++) {
            int row = i * 16 + o0 + oo;
            ya[oo] = *(const float2*)&Ya[row * MPIT + 2 * ko];
            yb[oo] = *(const float2*)&Yb[row * MPIT + 2 * ko];
        }
        #pragma unroll
        for (int bb = 0; bb < 2; bb++) {
            float xe0 = 0.5f * (xk[bb].x + xs[bb].x);
            float xo0 = 0.5f * (xk[bb].x - xs[bb].x);
            float xe1 = 0.5f * (xk[bb].y + xs[bb].y);
            float xo1 = 0.5f * (xk[bb].y - xs[bb].y);
            #pragma unroll
            for (int oo = 0; oo < 2; oo++) {
                acc [bb][oo][0] += xe0 * ya[oo].x + xo0 * yb[oo].x;
                accs[bb][oo][0] += xe0 * yb[oo].x - xo0 * ya[oo].x;
                acc [bb][oo][1] += xe1 * ya[oo].y + xo1 * yb[oo].y;
                accs[bb][oo][1] += xe1 * yb[oo].y - xo1 * ya[oo].y;
            }
        }
    }

    #pragma unroll
    for (int bb = 0; bb < 2; bb++)
        #pragma unroll
        for (int oo = 0; oo < 2; oo++) {
            float* zrow = g_Z + (size_t)((b0 + bb) * 16 + o0 + oo) * N3;
            #pragma unroll
            for (int kk = 0; kk < 2; kk++) {
                int k = k0 + 2 * ko + kk;
                if (k <= NHALF)              zrow[k]      = acc [bb][oo][kk];
                if (k >= 1 && k <= NHALF-1)  zrow[N3 - k] = accs[bb][oo][kk];
            }
        }
}

// ---------------- launcher ----------------------------------------------------
extern "C" void kernel_launch(void* const* d_in, const int* in_sizes, int n_in,
                              void* d_out, int out_size) {
    (void)in_sizes; (void)n_in; (void)out_size;
    static float2* bufB = nullptr;
    static float*  xh   = nullptr;
    static float*  z    = nullptr;
    static cudaStream_t s2 = nullptr;
    static cudaEvent_t  evFork = nullptr, evY = nullptr;
    if (!bufB) {   // first (uncaptured correctness) call only
        cudaGetSymbolAddress((void**)&bufB, g_bufB);
        cudaGetSymbolAddress((void**)&xh,   g_Xh);
        cudaGetSymbolAddress((void**)&z,    g_Z);
        cudaFuncSetAttribute(mix4, cudaFuncAttributeMaxDynamicSharedMemorySize,
                             (128 * MPIT * 2 + 256 * MPIT * 2) * (int)sizeof(float));
        cudaFuncSetAttribute(ykernel23, cudaFuncAttributeMaxDynamicSharedMemorySize,
                             (6912 + 12 * 49) * (int)sizeof(float2));
        cudaStreamCreateWithFlags(&s2, cudaStreamNonBlocking);
        cudaEventCreateWithFlags(&evFork, cudaEventDisableTiming);
        cudaEventCreateWithFlags(&evY,    cudaEventDisableTiming);
    }
    const float* x  = (const float*)d_in[0];   // [8,16,48,48,48]
    const float* wt = (const float*)d_in[2];   // [16,16,12,12,12]
    float* out = (float*)d_out;

    const int mix_smem = (128 * MPIT * 2 + 256 * MPIT * 2) * (int)sizeof(float);
    const int mix_grid = NHALF / MK + 1;       // 3457
    const int y_smem   = (6912 + 12 * 49) * (int)sizeof(float2);

    init_tw<<<(L * L + 255) / 256, 256>>>();

    // fork: Y path on side stream, overlapped with forward X passes
    cudaEventRecord(evFork, 0);
    cudaStreamWaitEvent(s2, evFork, 0);
    ykernel1<<<(CF * 12 * 12 * L + 255) / 256, 256, 0, s2>>>(wt);
    ykernel23<<<CF * 4, 256, y_smem, s2>>>();
    cudaEventRecord(evY, s2);

    // forward: x -> Xh (main stream)
    pass_wh<<<BF * L, 256>>>(x, bufB);
    pass_d <<<BF * L, 256>>>(bufB, xh, 1.f);

    // join: mix needs Yh
    cudaStreamWaitEvent(0, evY, 0);
    mix4<<<mix_grid, 256, mix_smem>>>();

    // inverse: Z -> out (scaled 1/N3)
    pass_wh<<<BF * L, 256>>>(z, bufB);
    pass_d <<<BF * L, 256>>>(bufB, out, 1.f / (float)N3);
}

// round 16
// speedup vs baseline: 1.2051x; 1.0327x over previous
#include <cuda_runtime.h>
#include <math.h>

#define L    48
#define LH   26                 // kept frequencies (Hermitian half: 0..25)
#define N3   110592             // 48^3
#define NHALF 55296             // N3/2
#define BF   128                // B*CIN  fields for x / Z
#define CF   256                // CIN*COUT fields for Y
#define PLH  59904              // 48*48*26
#define SQ2H 0.70710678118654752440f

// ---------------- scratch (static device memory) ---------------------------
__device__ float2 g_tw[L * L];
__device__ float2 g_tw1[L];
__device__ float2 g_emp[L];
__device__ float2 g_bufB[BF * PLH];            // 61 MB, layout [f][k_h][d][k_w]
__device__ float  g_Xh[BF * N3];
__device__ float  g_Yh[CF * N3];
__device__ float  g_Z [BF * N3];
__device__ float2 g_T1[CF * 12 * 12 * L];

// ---------------- twiddle init ---------------------------------------------
__global__ void init_tw() {
    int idx = blockIdx.x * blockDim.x + threadIdx.x;
    if (idx < L * L) {
        int k = idx / L, n = idx % L;
        int m = (k * n) % L;
        double a = -6.283185307179586476925286766559 * (double)m / (double)L;
        g_tw[idx] = make_float2((float)cos(a), (float)sin(a));
    }
    if (idx < L) {
        double a = -6.283185307179586476925286766559 * (double)idx / (double)L;
        float cx = (float)cos(a), cy = (float)sin(a);
        g_tw1[idx] = make_float2(cx, cy);
        g_emp[idx] = make_float2(cx - cy, cx + cy);
    }
}

// ---------------- 8-point FFT butterfly (W8 = e^{-2pi i/8}) -----------------
__device__ __forceinline__ void fft8c(const float2 q[8], float2 X[8]) {
    float t0r=q[0].x+q[4].x, t0i=q[0].y+q[4].y;
    float t1r=q[0].x-q[4].x, t1i=q[0].y-q[4].y;
    float t2r=q[2].x+q[6].x, t2i=q[2].y+q[6].y;
    float t3r=q[2].x-q[6].x, t3i=q[2].y-q[6].y;
    float E0r=t0r+t2r, E0i=t0i+t2i;
    float E2r=t0r-t2r, E2i=t0i-t2i;
    float E1r=t1r+t3i, E1i=t1i-t3r;
    float E3r=t1r-t3i, E3i=t1i+t3r;
    float u0r=q[1].x+q[5].x, u0i=q[1].y+q[5].y;
    float u1r=q[1].x-q[5].x, u1i=q[1].y-q[5].y;
    float u2r=q[3].x+q[7].x, u2i=q[3].y+q[7].y;
    float u3r=q[3].x-q[7].x, u3i=q[3].y-q[7].y;
    float O0r=u0r+u2r, O0i=u0i+u2i;
    float O2r=u0r-u2r, O2i=u0i-u2i;
    float O1r=u1r+u3i, O1i=u1i-u3r;
    float O3r=u1r-u3i, O3i=u1i+u3r;
    float W1r=SQ2H*(O1r+O1i), W1i=SQ2H*(O1i-O1r);
    float W2r=O2i,            W2i=-O2r;
    float W3r=SQ2H*(O3i-O3r), W3i=-SQ2H*(O3r+O3i);
    X[0]=make_float2(E0r+O0r, E0i+O0i);  X[4]=make_float2(E0r-O0r, E0i-O0i);
    X[1]=make_float2(E1r+W1r, E1i+W1i);  X[5]=make_float2(E1r-W1r, E1i-W1i);
    X[2]=make_float2(E2r+W2r, E2i+W2i);  X[6]=make_float2(E2r-W2r, E2i-W2i);
    X[3]=make_float2(E3r+W3r, E3i+W3i);  X[7]=make_float2(E3r-W3r, E3i-W3i);
}

// ============ fused pass W+H: real plane -> half spectrum ==================
// out layout [f][k_h][d][k_w] (d-major inner blocks for pass_d coalescing)
__global__ __launch_bounds__(256, 5) void pass_wh(
    const float* __restrict__ in, float2* __restrict__ out)
{
    __shared__ __align__(16) char ubuf[48 * 28 * sizeof(float2)];  // P / C overlay
    float  (*P)[50] = reinterpret_cast<float  (*)[50]>(ubuf);      // P[w][h]
    float2 (*C)[28] = reinterpret_cast<float2 (*)[28]>(ubuf);      // C[m_h][k_w]
    __shared__ float2 A2[L][L + 1];
    __shared__ float2 B2s[LH][L + 1];
    __shared__ float2 TWs[L];

    int t = threadIdx.x;
    int f = blockIdx.x / L, d = blockIdx.x % L;
    const float* src = in + (size_t)f * N3 + (size_t)d * 2304;

    if (t < L) TWs[t] = g_tw1[t];
    for (int idx = t; idx < L * L; idx += 256)
        P[idx % L][idx / L] = src[idx];          // transpose: P[w][h]
    __syncthreads();                             // (1)

    int tx = t & 15, ty = t >> 4;
    int k1r = ty & 7;
    bool g1 = (tx < 10);
    bool tp = (tx < 13);

    // ---- stage 1 (w, real radix-8): RFFT8 per (n2, j) -----------------------
    for (int u = t; u < 6 * 48; u += 256) {
        int n2 = u / 48, j = u - n2 * 48;
        float p[8];
        #pragma unroll
        for (int n1 = 0; n1 < 8; n1++) p[n1] = P[6 * n1 + n2][j];
        float t0=p[0]+p[4], t1=p[0]-p[4], t2=p[2]+p[6], t3=p[2]-p[6];
        float u0=p[1]+p[5], u1=p[1]-p[5], u2=p[3]+p[7], u3=p[3]-p[7];
        float E0=t0+t2, E2=t0-t2, O0=u0+u2, O2=u0-u2;
        float sa=SQ2H*(u1-u3), sb=SQ2H*(u1+u3);
        float2* arow = &A2[n2 * 8][0];
        const int pitch = L + 1;
        arow[0 * pitch + j] = make_float2(E0 + O0, 0.f);
        arow[1 * pitch + j] = make_float2(t1 + sa, -t3 - sb);
        arow[2 * pitch + j] = make_float2(E2, -O2);
        arow[3 * pitch + j] = make_float2(t1 - sa,  t3 - sb);
        arow[4 * pitch + j] = make_float2(E0 - O0, 0.f);
        arow[5 * pitch + j] = make_float2(t1 - sa, -(t3 - sb));
        arow[6 * pitch + j] = make_float2(E2,  O2);
        arow[7 * pitch + j] = make_float2(t1 + sa,  t3 + sb);
    }
    __syncthreads();                             // (2) — also fences last P reads

    // ---- stage 2 (w, radix-6): k_w = tx+16c (<26), h = ty+16a ---------------
    {
        float xr[3][2] = {{0.f}}, xi[3][2] = {{0.f}};
        int r8 = tx & 7;
        int i0 = 0, i1 = 0;
        int k3a = tx, k3b = tx + 16;
        #pragma unroll
        for (int n2 = 0; n2 < 6; n2++) {
            int arow = n2 * 8 + r8;
            float2 w0 = TWs[i0], w1 = TWs[i1];
            i0 += k3a; if (i0 >= L) i0 -= L;
            i1 += k3b; if (i1 >= L) i1 -= L;
            #pragma unroll
            for (int a = 0; a < 3; a++) {
                float2 v = A2[arow][ty + 16 * a];
                xr[a][0] += v.x * w0.x - v.y * w0.y;
                xi[a][0] += v.x * w0.y + v.y * w0.x;
                xr[a][1] += v.x * w1.x - v.y * w1.y;
                xi[a][1] += v.x * w1.y + v.y * w1.x;
            }
        }
        #pragma unroll
        for (int a = 0; a < 3; a++) {
            int h = ty + 16 * a;
            B2s[k3a][h] = make_float2(xr[a][0], xi[a][0]);
            if (g1) B2s[k3b][h] = make_float2(xr[a][1], xi[a][1]);
        }
    }
    __syncthreads();                             // (3)

    // ---- stage 3 (h, complex radix-8): FFT8 per (n2, k_w), C overlays P -----
    {
        bool act = (t < 6 * 26);
        if (act) {
            int n2 = t / 26, kw = t - n2 * 26;
            float2 q[8], X[8];
            #pragma unroll
            for (int n1 = 0; n1 < 8; n1++) q[n1] = B2s[kw][6 * n1 + n2];
            fft8c(q, X);
            #pragma unroll
            for (int k1 = 0; k1 < 8; k1++)
                C[n2 * 8 + k1][kw] = X[k1];
        }
    }
    __syncthreads();                             // (4)

    // ---- stage 4 (h, radix-6): k_w pair (2tx, 2tx+1), out [f][k_h][d][k_w] --
    if (tp) {
        float xr[3][2] = {{0.f}}, xi[3][2] = {{0.f}};
        int iw[3] = {0, 0, 0};
        #pragma unroll
        for (int n2 = 0; n2 < 6; n2++) {
            int arow = n2 * 8 + k1r;
            float4 vv = *(const float4*)&C[arow][2 * tx];   // one LDS.128
            #pragma unroll
            for (int a = 0; a < 3; a++) {
                float2 w = TWs[iw[a]];
                iw[a] += ty + 16 * a; if (iw[a] >= L) iw[a] -= L;
                xr[a][0] += vv.x * w.x - vv.y * w.y;
                xi[a][0] += vv.x * w.y + vv.y * w.x;
                xr[a][1] += vv.z * w.x - vv.w * w.y;
                xi[a][1] += vv.z * w.y + vv.w * w.x;
            }
        }
        float2* dstf = out + (size_t)f * PLH + (size_t)d * LH;
        #pragma unroll
        for (int a = 0; a < 3; a++) {
            int k2 = ty + 16 * a;
            float4 o4 = make_float4(xr[a][0], xi[a][0], xr[a][1], xi[a][1]);
            *(float4*)&dstf[(size_t)k2 * (L * LH) + 2 * tx] = o4;
        }
    }
}

// ============ pass D: complex, DFT along d, fold + Hermitian mirror write ===
// in layout [f][k_h][d][k_w] -> block (f,k_h) reads 9984B fully contiguous.
__global__ __launch_bounds__(256, 5) void pass_d(
    const float2* __restrict__ in, float* __restrict__ out, float scale)
{
    __shared__ __align__(16) float2 Q2[L][LH + 2];   // pitch 28, 16B rows
    __shared__ __align__(16) float2 A2[L][LH + 2];
    __shared__ float2 TWs[L];
    int t = threadIdx.x;
    int f = blockIdx.x / L, k2 = blockIdx.x % L;
    const float2* src = in + ((size_t)f * L + k2) * (L * LH);

    if (t < L) TWs[t] = g_tw1[t];
    // contiguous float4 staging: 1248 float2 = 624 float4; 26 even -> no row straddle
    for (int q4 = t; q4 < (L * LH) / 2; q4 += 256) {
        float4 v = *(const float4*)&src[q4 * 2];
        int e = q4 * 2;
        int row = e / LH, col = e - row * LH;
        *(float4*)&Q2[row][col] = v;
    }
    __syncthreads();

    int tx = t & 15, ty = t >> 4;
    bool tp = (tx < 13);

    // ---- stage 1 (d, complex radix-8): FFT8 per (n2, k_w) -------------------
    if (t < 6 * 26) {
        int n2 = t / 26, kw = t - n2 * 26;
        float2 q[8], X[8];
        #pragma unroll
        for (int n1 = 0; n1 < 8; n1++) q[n1] = Q2[6 * n1 + n2][kw];
        fft8c(q, X);
        #pragma unroll
        for (int k1 = 0; k1 < 8; k1++)
            A2[n2 * 8 + k1][kw] = X[k1];
    }
    __syncthreads();

    // ---- stage 2 (d, radix-6) + fold/mirror: k_w pair (2tx, 2tx+1) ----------
    if (tp) {
        int r8 = ty & 7;
        float xr[3][2] = {{0.f}}, xi[3][2] = {{0.f}};
        int iw[3] = {0, 0, 0};
        #pragma unroll
        for (int n2 = 0; n2 < 6; n2++) {
            int arow = n2 * 8 + r8;
            float4 vv = *(const float4*)&A2[arow][2 * tx];
            #pragma unroll
            for (int a = 0; a < 3; a++) {
                float2 w = TWs[iw[a]];
                iw[a] += ty + 16 * a; if (iw[a] >= L) iw[a] -= L;
                xr[a][0] += vv.x * w.x - vv.y * w.y;
                xi[a][0] += vv.x * w.y + vv.y * w.x;
                xr[a][1] += vv.z * w.x - vv.w * w.y;
                xi[a][1] += vv.z * w.y + vv.w * w.x;
            }
        }
        int mk2 = (k2 == 0) ? 0 : L - k2;
        float* dstD = out + (size_t)f * N3 + (size_t)k2 * L;
        float* dstM = out + (size_t)f * N3 + (size_t)mk2 * L;
        #pragma unroll
        for (int a = 0; a < 3; a++) {
            int k1 = ty + 16 * a;
            int mk1 = (k1 == 0) ? 0 : L - k1;
            float D0 = scale * (xr[a][0] - xi[a][0]);
            float D1 = scale * (xr[a][1] - xi[a][1]);
            float M0 = scale * (xr[a][0] + xi[a][0]);
            float M1 = scale * (xr[a][1] + xi[a][1]);
            *(float2*)&dstD[(size_t)k1 * 2304 + 2 * tx] = make_float2(D0, D1);
            if (tx == 0) {
                dstM[(size_t)mk1 * 2304 + 0]  = M0;
                dstM[(size_t)mk1 * 2304 + 47] = M1;
            } else {
                dstM[(size_t)mk1 * 2304 + 48 - 2 * tx] = M0;
                dstM[(size_t)mk1 * 2304 + 47 - 2 * tx] = M1;
            }
        }
    }
}

// ---------------- Y path -----------------------------------------------------
__global__ void ykernel1(const float* __restrict__ w) {
    int idx = blockIdx.x * blockDim.x + threadIdx.x;
    if (idx >= CF * 12 * 12 * L) return;
    int k3 = idx % L;
    int r  = idx / L;
    const float* wp = w + r * 12;
    float ar = 0.f, ai = 0.f;
    #pragma unroll
    for (int n3 = 0; n3 < 12; n3++) {
        float2 e = g_tw[k3 * L + n3];
        float  v = wp[n3];
        ar += v * e.x;  ai += v * e.y;
    }
    g_T1[idx] = make_float2(ar, ai);
}

__global__ __launch_bounds__(256) void ykernel23() {
    extern __shared__ float2 ysm[];
    float2* T1s = ysm;                      // 6912 float2
    float2* T2c = ysm + 6912;               // [n1*49 + k3]
    __shared__ float2 TWs[L];
    __shared__ float2 EMPs[L];

    int t  = threadIdx.x;
    int io = blockIdx.x >> 2;
    int kt = blockIdx.x & 3;

    if (t < L) { TWs[t] = g_tw1[t]; EMPs[t] = g_emp[t]; }
    const float2* src = g_T1 + (size_t)io * 6912;
    for (int idx = t; idx < 6912; idx += 256) T1s[idx] = src[idx];
    __syncthreads();

    int tx = t & 15, ty = t >> 4;

    for (int kk = 0; kk < 12; kk++) {
        int k2 = kt * 12 + kk;

        for (int idx = t; idx < 576; idx += 256) {
            int n1 = idx / 48, k3 = idx - n1 * 48;
            const float2* tp2 = T1s + n1 * 576 + k3;
            float ar = 0.f, ai = 0.f;
            int iw = 0;
            #pragma unroll
            for (int n2 = 0; n2 < 12; n2++) {
                float2 v = tp2[n2 * 48];
                float2 e = TWs[iw];
                iw += k2; if (iw >= L) iw -= L;
                ar += v.x * e.x - v.y * e.y;
                ai += v.x * e.y + v.y * e.x;
            }
            T2c[n1 * 49 + k3] = make_float2(ar, ai);
        }
        __syncthreads();

        {
            float acc[3][3] = {{0.f}};
            int iw2[3] = {0, 0, 0};
            #pragma unroll
            for (int n1 = 0; n1 < 12; n1++) {
                float2 tv[3];
                #pragma unroll
                for (int b = 0; b < 3; b++) tv[b] = T2c[n1 * 49 + tx + 16 * b];
                #pragma unroll
                for (int a = 0; a < 3; a++) {
                    float2 e = EMPs[iw2[a]];
                    iw2[a] += ty + 16 * a; if (iw2[a] >= L) iw2[a] -= L;
                    #pragma unroll
                    for (int b = 0; b < 3; b++)
                        acc[a][b] += tv[b].x * e.x - tv[b].y * e.y;
                }
            }
            #pragma unroll
            for (int a = 0; a < 3; a++)
                #pragma unroll
                for (int b = 0; b < 3; b++)
                    g_Yh[(size_t)io * N3 + (size_t)(ty + 16 * a) * 2304
                         + (size_t)k2 * 48 + tx + 16 * b] = acc[a][b];
        }
        __syncthreads();
    }
}

// ---------------- mix4: 2b x 2o x 2k register tile, MK=16 --------------------
#define MK    16
#define MPIT  18
__global__ __launch_bounds__(256) void mix4() {
    extern __shared__ float sm[];
    float* Xa = sm;                        // [128][MPIT]
    float* Xb = Xa + 128 * MPIT;
    float* Ya = Xb + 128 * MPIT;           // [256][MPIT]
    float* Yb = Ya + 256 * MPIT;

    int t  = threadIdx.x;
    int k0 = blockIdx.x * MK;

    for (int q = t; q < 128 * MK; q += 256) {
        int kk = q & 15, bi = q >> 4;
        int k = k0 + kk; if (k > NHALF) k = NHALF;
        int sk = (k == 0) ? 0 : (N3 - k);
        Xa[bi * MPIT + kk] = g_Xh[(size_t)bi * N3 + k];
        Xb[bi * MPIT + kk] = g_Xh[(size_t)bi * N3 + sk];
    }
    for (int q = t; q < 256 * MK; q += 256) {
        int kk = q & 15, io = q >> 4;
        int k = k0 + kk; if (k > NHALF) k = NHALF;
        int sk = (k == 0) ? 0 : (N3 - k);
        Ya[io * MPIT + kk] = g_Yh[(size_t)io * N3 + k];
        Yb[io * MPIT + kk] = g_Yh[(size_t)io * N3 + sk];
    }
    __syncthreads();

    int ko = t & 7;            // k-pair: kk = 2*ko + {0,1}
    int b0 = ((t >> 3) & 3) * 2;
    int o0 = (t >> 5) * 2;

    float acc[2][2][2] = {{{0.f}}}, accs[2][2][2] = {{{0.f}}};
    #pragma unroll 4
    for (int i = 0; i < 16; i++) {
        float2 xk[2], xs[2], ya[2], yb[2];
        #pragma unroll
        for (int bb = 0; bb < 2; bb++) {
            int row = (b0 + bb) * 16 + i;
            xk[bb] = *(const float2*)&Xa[row * MPIT + 2 * ko];
            xs[bb] = *(const float2*)&Xb[row * MPIT + 2 * ko];
        }
        #pragma unroll
        for (int oo = 0; oo < 2; oo++) {
            int row = i * 16 + o0 + oo;
            ya[oo] = *(const float2*)&Ya[row * MPIT + 2 * ko];
            yb[oo] = *(const float2*)&Yb[row * MPIT + 2 * ko];
        }
        #pragma unroll
        for (int bb = 0; bb < 2; bb++) {
            float xe0 = 0.5f * (xk[bb].x + xs[bb].x);
            float xo0 = 0.5f * (xk[bb].x - xs[bb].x);
            float xe1 = 0.5f * (xk[bb].y + xs[bb].y);
            float xo1 = 0.5f * (xk[bb].y - xs[bb].y);
            #pragma unroll
            for (int oo = 0; oo < 2; oo++) {
                acc [bb][oo][0] += xe0 * ya[oo].x + xo0 * yb[oo].x;
                accs[bb][oo][0] += xe0 * yb[oo].x - xo0 * ya[oo].x;
                acc [bb][oo][1] += xe1 * ya[oo].y + xo1 * yb[oo].y;
                accs[bb][oo][1] += xe1 * yb[oo].y - xo1 * ya[oo].y;
            }
        }
    }

    #pragma unroll
    for (int bb = 0; bb < 2; bb++)
        #pragma unroll
        for (int oo = 0; oo < 2; oo++) {
            float* zrow = g_Z + (size_t)((b0 + bb) * 16 + o0 + oo) * N3;
            #pragma unroll
            for (int kk = 0; kk < 2; kk++) {
                int k = k0 + 2 * ko + kk;
                if (k <= NHALF)              zrow[k]      = acc [bb][oo][kk];
                if (k >= 1 && k <= NHALF-1)  zrow[N3 - k] = accs[bb][oo][kk];
            }
        }
}

// ---------------- launcher ----------------------------------------------------
extern "C" void kernel_launch(void* const* d_in, const int* in_sizes, int n_in,
                              void* d_out, int out_size) {
    (void)in_sizes; (void)n_in; (void)out_size;
    static float2* bufB = nullptr;
    static float*  xh   = nullptr;
    static float*  z    = nullptr;
    static cudaStream_t s2 = nullptr;
    static cudaEvent_t  evFork = nullptr, evY = nullptr;
    if (!bufB) {   // first (uncaptured correctness) call only
        cudaGetSymbolAddress((void**)&bufB, g_bufB);
        cudaGetSymbolAddress((void**)&xh,   g_Xh);
        cudaGetSymbolAddress((void**)&z,    g_Z);
        cudaFuncSetAttribute(mix4, cudaFuncAttributeMaxDynamicSharedMemorySize,
                             (128 * MPIT * 2 + 256 * MPIT * 2) * (int)sizeof(float));
        cudaFuncSetAttribute(ykernel23, cudaFuncAttributeMaxDynamicSharedMemorySize,
                             (6912 + 12 * 49) * (int)sizeof(float2));
        cudaStreamCreateWithFlags(&s2, cudaStreamNonBlocking);
        cudaEventCreateWithFlags(&evFork, cudaEventDisableTiming);
        cudaEventCreateWithFlags(&evY,    cudaEventDisableTiming);
    }
    const float* x  = (const float*)d_in[0];   // [8,16,48,48,48]
    const float* wt = (const float*)d_in[2];   // [16,16,12,12,12]
    float* out = (float*)d_out;

    const int mix_smem = (128 * MPIT * 2 + 256 * MPIT * 2) * (int)sizeof(float);
    const int mix_grid = NHALF / MK + 1;       // 3457
    const int y_smem   = (6912 + 12 * 49) * (int)sizeof(float2);

    init_tw<<<(L * L + 255) / 256, 256>>>();

    // fork: Y path on side stream, overlapped with forward X passes
    cudaEventRecord(evFork, 0);
    cudaStreamWaitEvent(s2, evFork, 0);
    ykernel1<<<(CF * 12 * 12 * L + 255) / 256, 256, 0, s2>>>(wt);
    ykernel23<<<CF * 4, 256, y_smem, s2>>>();
    cudaEventRecord(evY, s2);

    // forward: x -> Xh (main stream)
    pass_wh<<<BF * L, 256>>>(x, bufB);
    pass_d <<<BF * L, 256>>>(bufB, xh, 1.f);

    // join: mix needs Yh
    cudaStreamWaitEvent(0, evY, 0);
    mix4<<<mix_grid, 256, mix_smem>>>();

    // inverse: Z -> out (scaled 1/N3)
    pass_wh<<<BF * L, 256>>>(z, bufB);
    pass_d <<<BF * L, 256>>>(bufB, out, 1.f / (float)N3);
}

// round 17
// speedup vs baseline: 1.2805x; 1.0626x over previous
#include <cuda_runtime.h>
#include <math.h>

#define L    48
#define LH   26                 // kept frequencies (Hermitian half: 0..25)
#define N3   110592             // 48^3
#define NHALF 55296             // N3/2
#define BF   128                // B*CIN  fields for x / Z
#define CF   256                // CIN*COUT fields for Y
#define PLH  59904              // 48*48*26
#define SQ2H 0.70710678118654752440f

// ---------------- scratch (static device memory) ---------------------------
__device__ float2 g_tw[L * L];
__device__ float2 g_tw1[L];
__device__ float2 g_emp[L];
__device__ float2 g_bufB[BF * PLH];            // 61 MB, layout [f][k_h][d][k_w]
__device__ float  g_Xh[BF * N3];
__device__ float  g_Yh[CF * N3];
__device__ float  g_Z [BF * N3];
__device__ float2 g_T1[CF * 12 * 12 * L];

// ---------------- twiddle init ---------------------------------------------
__global__ void init_tw() {
    int idx = blockIdx.x * blockDim.x + threadIdx.x;
    if (idx < L * L) {
        int k = idx / L, n = idx % L;
        int m = (k * n) % L;
        double a = -6.283185307179586476925286766559 * (double)m / (double)L;
        g_tw[idx] = make_float2((float)cos(a), (float)sin(a));
    }
    if (idx < L) {
        double a = -6.283185307179586476925286766559 * (double)idx / (double)L;
        float cx = (float)cos(a), cy = (float)sin(a);
        g_tw1[idx] = make_float2(cx, cy);
        g_emp[idx] = make_float2(cx - cy, cx + cy);
    }
}

// ---------------- 8-point FFT butterfly (W8 = e^{-2pi i/8}) -----------------
__device__ __forceinline__ void fft8c(const float2 q[8], float2 X[8]) {
    float t0r=q[0].x+q[4].x, t0i=q[0].y+q[4].y;
    float t1r=q[0].x-q[4].x, t1i=q[0].y-q[4].y;
    float t2r=q[2].x+q[6].x, t2i=q[2].y+q[6].y;
    float t3r=q[2].x-q[6].x, t3i=q[2].y-q[6].y;
    float E0r=t0r+t2r, E0i=t0i+t2i;
    float E2r=t0r-t2r, E2i=t0i-t2i;
    float E1r=t1r+t3i, E1i=t1i-t3r;
    float E3r=t1r-t3i, E3i=t1i+t3r;
    float u0r=q[1].x+q[5].x, u0i=q[1].y+q[5].y;
    float u1r=q[1].x-q[5].x, u1i=q[1].y-q[5].y;
    float u2r=q[3].x+q[7].x, u2i=q[3].y+q[7].y;
    float u3r=q[3].x-q[7].x, u3i=q[3].y-q[7].y;
    float O0r=u0r+u2r, O0i=u0i+u2i;
    float O2r=u0r-u2r, O2i=u0i-u2i;
    float O1r=u1r+u3i, O1i=u1i-u3r;
    float O3r=u1r-u3i, O3i=u1i+u3r;
    float W1r=SQ2H*(O1r+O1i), W1i=SQ2H*(O1i-O1r);
    float W2r=O2i,            W2i=-O2r;
    float W3r=SQ2H*(O3i-O3r), W3i=-SQ2H*(O3r+O3i);
    X[0]=make_float2(E0r+O0r, E0i+O0i);  X[4]=make_float2(E0r-O0r, E0i-O0i);
    X[1]=make_float2(E1r+W1r, E1i+W1i);  X[5]=make_float2(E1r-W1r, E1i-W1i);
    X[2]=make_float2(E2r+W2r, E2i+W2i);  X[6]=make_float2(E2r-W2r, E2i-W2i);
    X[3]=make_float2(E3r+W3r, E3i+W3i);  X[7]=make_float2(E3r-W3r, E3i-W3i);
}

// ============ fused pass W+H: real plane -> half spectrum ==================
__global__ __launch_bounds__(256, 5) void pass_wh(
    const float* __restrict__ in, float2* __restrict__ out)
{
    __shared__ __align__(16) char ubuf[48 * 28 * sizeof(float2)];  // P / C overlay
    float  (*P)[50] = reinterpret_cast<float  (*)[50]>(ubuf);      // P[w][h]
    float2 (*C)[28] = reinterpret_cast<float2 (*)[28]>(ubuf);      // C[m_h][k_w]
    __shared__ float2 A2[L][L + 1];
    __shared__ float2 B2s[LH][L + 1];
    __shared__ float2 TWs[L];

    int t = threadIdx.x;
    int f = blockIdx.x / L, d = blockIdx.x % L;
    const float* src = in + (size_t)f * N3 + (size_t)d * 2304;

    if (t < L) TWs[t] = g_tw1[t];
    for (int idx = t; idx < L * L; idx += 256)
        P[idx % L][idx / L] = src[idx];          // transpose: P[w][h]
    __syncthreads();                             // (1)

    int tx = t & 15, ty = t >> 4;
    int k1r = ty & 7;
    bool g1 = (tx < 10);
    bool tp = (tx < 13);

    // ---- stage 1 (w, real radix-8): RFFT8 per (n2, j) -----------------------
    for (int u = t; u < 6 * 48; u += 256) {
        int n2 = u / 48, j = u - n2 * 48;
        float p[8];
        #pragma unroll
        for (int n1 = 0; n1 < 8; n1++) p[n1] = P[6 * n1 + n2][j];
        float t0=p[0]+p[4], t1=p[0]-p[4], t2=p[2]+p[6], t3=p[2]-p[6];
        float u0=p[1]+p[5], u1=p[1]-p[5], u2=p[3]+p[7], u3=p[3]-p[7];
        float E0=t0+t2, E2=t0-t2, O0=u0+u2, O2=u0-u2;
        float sa=SQ2H*(u1-u3), sb=SQ2H*(u1+u3);
        float2* arow = &A2[n2 * 8][0];
        const int pitch = L + 1;
        arow[0 * pitch + j] = make_float2(E0 + O0, 0.f);
        arow[1 * pitch + j] = make_float2(t1 + sa, -t3 - sb);
        arow[2 * pitch + j] = make_float2(E2, -O2);
        arow[3 * pitch + j] = make_float2(t1 - sa,  t3 - sb);
        arow[4 * pitch + j] = make_float2(E0 - O0, 0.f);
        arow[5 * pitch + j] = make_float2(t1 - sa, -(t3 - sb));
        arow[6 * pitch + j] = make_float2(E2,  O2);
        arow[7 * pitch + j] = make_float2(t1 + sa,  t3 + sb);
    }
    __syncthreads();                             // (2)

    // ---- stage 2 (w, radix-6): k_w = tx+16c (<26), h = ty+16a ---------------
    {
        float xr[3][2] = {{0.f}}, xi[3][2] = {{0.f}};
        int r8 = tx & 7;
        int i0 = 0, i1 = 0;
        int k3a = tx, k3b = tx + 16;
        #pragma unroll
        for (int n2 = 0; n2 < 6; n2++) {
            int arow = n2 * 8 + r8;
            float2 w0 = TWs[i0], w1 = TWs[i1];
            i0 += k3a; if (i0 >= L) i0 -= L;
            i1 += k3b; if (i1 >= L) i1 -= L;
            #pragma unroll
            for (int a = 0; a < 3; a++) {
                float2 v = A2[arow][ty + 16 * a];
                xr[a][0] += v.x * w0.x - v.y * w0.y;
                xi[a][0] += v.x * w0.y + v.y * w0.x;
                xr[a][1] += v.x * w1.x - v.y * w1.y;
                xi[a][1] += v.x * w1.y + v.y * w1.x;
            }
        }
        #pragma unroll
        for (int a = 0; a < 3; a++) {
            int h = ty + 16 * a;
            B2s[k3a][h] = make_float2(xr[a][0], xi[a][0]);
            if (g1) B2s[k3b][h] = make_float2(xr[a][1], xi[a][1]);
        }
    }
    __syncthreads();                             // (3)

    // ---- stage 3 (h, complex radix-8): FFT8 per (n2, k_w), C overlays P -----
    {
        bool act = (t < 6 * 26);
        if (act) {
            int n2 = t / 26, kw = t - n2 * 26;
            float2 q[8], X[8];
            #pragma unroll
            for (int n1 = 0; n1 < 8; n1++) q[n1] = B2s[kw][6 * n1 + n2];
            fft8c(q, X);
            #pragma unroll
            for (int k1 = 0; k1 < 8; k1++)
                C[n2 * 8 + k1][kw] = X[k1];
        }
    }
    __syncthreads();                             // (4)

    // ---- stage 4 (h, radix-6): k_w pair (2tx, 2tx+1) ------------------------
    if (tp) {
        float xr[3][2] = {{0.f}}, xi[3][2] = {{0.f}};
        int iw[3] = {0, 0, 0};
        #pragma unroll
        for (int n2 = 0; n2 < 6; n2++) {
            int arow = n2 * 8 + k1r;
            float4 vv = *(const float4*)&C[arow][2 * tx];
            #pragma unroll
            for (int a = 0; a < 3; a++) {
                float2 w = TWs[iw[a]];
                iw[a] += ty + 16 * a; if (iw[a] >= L) iw[a] -= L;
                xr[a][0] += vv.x * w.x - vv.y * w.y;
                xi[a][0] += vv.x * w.y + vv.y * w.x;
                xr[a][1] += vv.z * w.x - vv.w * w.y;
                xi[a][1] += vv.z * w.y + vv.w * w.x;
            }
        }
        float2* dstf = out + (size_t)f * PLH + (size_t)d * LH;
        #pragma unroll
        for (int a = 0; a < 3; a++) {
            int k2 = ty + 16 * a;
            float4 o4 = make_float4(xr[a][0], xi[a][0], xr[a][1], xi[a][1]);
            *(float4*)&dstf[(size_t)k2 * (L * LH) + 2 * tx] = o4;
        }
    }
}

// ============ pass D: complex, DFT along d, fold + Hermitian mirror write ===
__global__ __launch_bounds__(256, 5) void pass_d(
    const float2* __restrict__ in, float* __restrict__ out, float scale)
{
    __shared__ __align__(16) float2 Q2[L][LH + 2];
    __shared__ __align__(16) float2 A2[L][LH + 2];
    __shared__ float2 TWs[L];
    int t = threadIdx.x;
    int f = blockIdx.x / L, k2 = blockIdx.x % L;
    const float2* src = in + ((size_t)f * L + k2) * (L * LH);

    if (t < L) TWs[t] = g_tw1[t];
    for (int q4 = t; q4 < (L * LH) / 2; q4 += 256) {
        float4 v = *(const float4*)&src[q4 * 2];
        int e = q4 * 2;
        int row = e / LH, col = e - row * LH;
        *(float4*)&Q2[row][col] = v;
    }
    __syncthreads();

    int tx = t & 15, ty = t >> 4;
    bool tp = (tx < 13);

    if (t < 6 * 26) {
        int n2 = t / 26, kw = t - n2 * 26;
        float2 q[8], X[8];
        #pragma unroll
        for (int n1 = 0; n1 < 8; n1++) q[n1] = Q2[6 * n1 + n2][kw];
        fft8c(q, X);
        #pragma unroll
        for (int k1 = 0; k1 < 8; k1++)
            A2[n2 * 8 + k1][kw] = X[k1];
    }
    __syncthreads();

    if (tp) {
        int r8 = ty & 7;
        float xr[3][2] = {{0.f}}, xi[3][2] = {{0.f}};
        int iw[3] = {0, 0, 0};
        #pragma unroll
        for (int n2 = 0; n2 < 6; n2++) {
            int arow = n2 * 8 + r8;
            float4 vv = *(const float4*)&A2[arow][2 * tx];
            #pragma unroll
            for (int a = 0; a < 3; a++) {
                float2 w = TWs[iw[a]];
                iw[a] += ty + 16 * a; if (iw[a] >= L) iw[a] -= L;
                xr[a][0] += vv.x * w.x - vv.y * w.y;
                xi[a][0] += vv.x * w.y + vv.y * w.x;
                xr[a][1] += vv.z * w.x - vv.w * w.y;
                xi[a][1] += vv.z * w.y + vv.w * w.x;
            }
        }
        int mk2 = (k2 == 0) ? 0 : L - k2;
        float* dstD = out + (size_t)f * N3 + (size_t)k2 * L;
        float* dstM = out + (size_t)f * N3 + (size_t)mk2 * L;
        #pragma unroll
        for (int a = 0; a < 3; a++) {
            int k1 = ty + 16 * a;
            int mk1 = (k1 == 0) ? 0 : L - k1;
            float D0 = scale * (xr[a][0] - xi[a][0]);
            float D1 = scale * (xr[a][1] - xi[a][1]);
            float M0 = scale * (xr[a][0] + xi[a][0]);
            float M1 = scale * (xr[a][1] + xi[a][1]);
            *(float2*)&dstD[(size_t)k1 * 2304 + 2 * tx] = make_float2(D0, D1);
            if (tx == 0) {
                dstM[(size_t)mk1 * 2304 + 0]  = M0;
                dstM[(size_t)mk1 * 2304 + 47] = M1;
            } else {
                dstM[(size_t)mk1 * 2304 + 48 - 2 * tx] = M0;
                dstM[(size_t)mk1 * 2304 + 47 - 2 * tx] = M1;
            }
        }
    }
}

// ---------------- Y path -----------------------------------------------------
__global__ void ykernel1(const float* __restrict__ w) {
    int idx = blockIdx.x * blockDim.x + threadIdx.x;
    if (idx >= CF * 12 * 12 * L) return;
    int k3 = idx % L;
    int r  = idx / L;
    const float* wp = w + r * 12;
    float ar = 0.f, ai = 0.f;
    #pragma unroll
    for (int n3 = 0; n3 < 12; n3++) {
        float2 e = g_tw[k3 * L + n3];
        float  v = wp[n3];
        ar += v * e.x;  ai += v * e.y;
    }
    g_T1[idx] = make_float2(ar, ai);
}

__global__ __launch_bounds__(256) void ykernel23() {
    extern __shared__ float2 ysm[];
    float2* T1s = ysm;
    float2* T2c = ysm + 6912;
    __shared__ float2 TWs[L];
    __shared__ float2 EMPs[L];

    int t  = threadIdx.x;
    int io = blockIdx.x >> 2;
    int kt = blockIdx.x & 3;

    if (t < L) { TWs[t] = g_tw1[t]; EMPs[t] = g_emp[t]; }
    const float2* src = g_T1 + (size_t)io * 6912;
    for (int idx = t; idx < 6912; idx += 256) T1s[idx] = src[idx];
    __syncthreads();

    int tx = t & 15, ty = t >> 4;

    for (int kk = 0; kk < 12; kk++) {
        int k2 = kt * 12 + kk;

        for (int idx = t; idx < 576; idx += 256) {
            int n1 = idx / 48, k3 = idx - n1 * 48;
            const float2* tp2 = T1s + n1 * 576 + k3;
            float ar = 0.f, ai = 0.f;
            int iw = 0;
            #pragma unroll
            for (int n2 = 0; n2 < 12; n2++) {
                float2 v = tp2[n2 * 48];
                float2 e = TWs[iw];
                iw += k2; if (iw >= L) iw -= L;
                ar += v.x * e.x - v.y * e.y;
                ai += v.x * e.y + v.y * e.x;
            }
            T2c[n1 * 49 + k3] = make_float2(ar, ai);
        }
        __syncthreads();

        {
            float acc[3][3] = {{0.f}};
            int iw2[3] = {0, 0, 0};
            #pragma unroll
            for (int n1 = 0; n1 < 12; n1++) {
                float2 tv[3];
                #pragma unroll
                for (int b = 0; b < 3; b++) tv[b] = T2c[n1 * 49 + tx + 16 * b];
                #pragma unroll
                for (int a = 0; a < 3; a++) {
                    float2 e = EMPs[iw2[a]];
                    iw2[a] += ty + 16 * a; if (iw2[a] >= L) iw2[a] -= L;
                    #pragma unroll
                    for (int b = 0; b < 3; b++)
                        acc[a][b] += tv[b].x * e.x - tv[b].y * e.y;
                }
            }
            #pragma unroll
            for (int a = 0; a < 3; a++)
                #pragma unroll
                for (int b = 0; b < 3; b++)
                    g_Yh[(size_t)io * N3 + (size_t)(ty + 16 * a) * 2304
                         + (size_t)k2 * 48 + tx + 16 * b] = acc[a][b];
        }
        __syncthreads();
    }
}

// ---------------- mix5: vectorized global loads/stores, MK=16 ----------------
#define MK    16
#define MPIT  18
__global__ __launch_bounds__(256) void mix5() {
    extern __shared__ float sm[];
    float* Xa = sm;                        // [128][MPIT]
    float* Xb = Xa + 128 * MPIT;
    float* Ya = Xb + 128 * MPIT;           // [256][MPIT]
    float* Yb = Ya + 256 * MPIT;

    int t  = threadIdx.x;
    int k0 = blockIdx.x * MK;
    bool edge = (k0 + MK - 1 > NHALF);     // only the last block

    if (!edge) {
        // X direct + mirror, vectorized (mirror kk=1..15 from reversed quads)
        for (int v = t; v < 512; v += 256) {
            int bi = v >> 2, q = v & 3;
            float4 d4 = *(const float4*)&g_Xh[(size_t)bi * N3 + k0 + 4 * q];
            float* da = &Xa[bi * MPIT + 4 * q];
            da[0] = d4.x; da[1] = d4.y; da[2] = d4.z; da[3] = d4.w;
            float4 m4 = *(const float4*)&g_Xh[(size_t)bi * N3 + (N3 - k0 - 16) + 4 * q];
            float* mb = &Xb[bi * MPIT];
            int kb = 16 - 4 * q;           // kk for component c is kb - c
            if (q == 0) { mb[15] = m4.y; mb[14] = m4.z; mb[13] = m4.w; }
            else { mb[kb] = m4.x; mb[kb - 1] = m4.y; mb[kb - 2] = m4.z; mb[kb - 3] = m4.w; }
        }
        if (t < 128)
            Xb[t * MPIT] = g_Xh[(size_t)t * N3 + ((k0 == 0) ? 0 : N3 - k0)];
        // Y direct + mirror
        for (int v = t; v < 1024; v += 256) {
            int io = v >> 2, q = v & 3;
            float4 d4 = *(const float4*)&g_Yh[(size_t)io * N3 + k0 + 4 * q];
            float* da = &Ya[io * MPIT + 4 * q];
            da[0] = d4.x; da[1] = d4.y; da[2] = d4.z; da[3] = d4.w;
            float4 m4 = *(const float4*)&g_Yh[(size_t)io * N3 + (N3 - k0 - 16) + 4 * q];
            float* mb = &Yb[io * MPIT];
            int kb = 16 - 4 * q;
            if (q == 0) { mb[15] = m4.y; mb[14] = m4.z; mb[13] = m4.w; }
            else { mb[kb] = m4.x; mb[kb - 1] = m4.y; mb[kb - 2] = m4.z; mb[kb - 3] = m4.w; }
        }
        if (t < 256)
            Yb[t * MPIT] = g_Yh[(size_t)t * N3 + ((k0 == 0) ? 0 : N3 - k0)];
    } else {
        for (int q = t; q < 128 * MK; q += 256) {
            int kk = q & 15, bi = q >> 4;
            int k = k0 + kk; if (k > NHALF) k = NHALF;
            int sk = (k == 0) ? 0 : (N3 - k);
            Xa[bi * MPIT + kk] = g_Xh[(size_t)bi * N3 + k];
            Xb[bi * MPIT + kk] = g_Xh[(size_t)bi * N3 + sk];
        }
        for (int q = t; q < 256 * MK; q += 256) {
            int kk = q & 15, io = q >> 4;
            int k = k0 + kk; if (k > NHALF) k = NHALF;
            int sk = (k == 0) ? 0 : (N3 - k);
            Ya[io * MPIT + kk] = g_Yh[(size_t)io * N3 + k];
            Yb[io * MPIT + kk] = g_Yh[(size_t)io * N3 + sk];
        }
    }
    __syncthreads();

    int ko = t & 7;            // k-pair: kk = 2*ko + {0,1}
    int b0 = ((t >> 3) & 3) * 2;
    int o0 = (t >> 5) * 2;

    float acc[2][2][2] = {{{0.f}}}, accs[2][2][2] = {{{0.f}}};
    #pragma unroll 4
    for (int i = 0; i < 16; i++) {
        float2 xk[2], xs[2], ya[2], yb[2];
        #pragma unroll
        for (int bb = 0; bb < 2; bb++) {
            int row = (b0 + bb) * 16 + i;
            xk[bb] = *(const float2*)&Xa[row * MPIT + 2 * ko];
            xs[bb] = *(const float2*)&Xb[row * MPIT + 2 * ko];
        }
        #pragma unroll
        for (int oo = 0; oo < 2; oo++) {
            int row = i * 16 + o0 + oo;
            ya[oo] = *(const float2*)&Ya[row * MPIT + 2 * ko];
            yb[oo] = *(const float2*)&Yb[row * MPIT + 2 * ko];
        }
        #pragma unroll
        for (int bb = 0; bb < 2; bb++) {
            float xe0 = 0.5f * (xk[bb].x + xs[bb].x);
            float xo0 = 0.5f * (xk[bb].x - xs[bb].x);
            float xe1 = 0.5f * (xk[bb].y + xs[bb].y);
            float xo1 = 0.5f * (xk[bb].y - xs[bb].y);
            #pragma unroll
            for (int oo = 0; oo < 2; oo++) {
                acc [bb][oo][0] += xe0 * ya[oo].x + xo0 * yb[oo].x;
                accs[bb][oo][0] += xe0 * yb[oo].x - xo0 * ya[oo].x;
                acc [bb][oo][1] += xe1 * ya[oo].y + xo1 * yb[oo].y;
                accs[bb][oo][1] += xe1 * yb[oo].y - xo1 * ya[oo].y;
            }
        }
    }

    if (!edge) {
        int k = k0 + 2 * ko;
        #pragma unroll
        for (int bb = 0; bb < 2; bb++)
            #pragma unroll
            for (int oo = 0; oo < 2; oo++) {
                float* zrow = g_Z + (size_t)((b0 + bb) * 16 + o0 + oo) * N3;
                *(float2*)&zrow[k] = make_float2(acc[bb][oo][0], acc[bb][oo][1]);
                if (k >= 1) zrow[N3 - k] = accs[bb][oo][0];     // fails only k0=0,ko=0
                zrow[N3 - k - 1] = accs[bb][oo][1];             // k+1 in [1, NHALF-1]
            }
    } else {
        #pragma unroll
        for (int bb = 0; bb < 2; bb++)
            #pragma unroll
            for (int oo = 0; oo < 2; oo++) {
                float* zrow = g_Z + (size_t)((b0 + bb) * 16 + o0 + oo) * N3;
                #pragma unroll
                for (int kk = 0; kk < 2; kk++) {
                    int k = k0 + 2 * ko + kk;
                    if (k <= NHALF)              zrow[k]      = acc [bb][oo][kk];
                    if (k >= 1 && k <= NHALF-1)  zrow[N3 - k] = accs[bb][oo][kk];
                }
            }
    }
}

// ---------------- launcher ----------------------------------------------------
extern "C" void kernel_launch(void* const* d_in, const int* in_sizes, int n_in,
                              void* d_out, int out_size) {
    (void)in_sizes; (void)n_in; (void)out_size;
    static float2* bufB = nullptr;
    static float*  xh   = nullptr;
    static float*  z    = nullptr;
    static cudaStream_t s2 = nullptr;
    static cudaEvent_t  evFork = nullptr, evY = nullptr;
    if (!bufB) {   // first (uncaptured correctness) call only
        cudaGetSymbolAddress((void**)&bufB, g_bufB);
        cudaGetSymbolAddress((void**)&xh,   g_Xh);
        cudaGetSymbolAddress((void**)&z,    g_Z);
        cudaFuncSetAttribute(mix5, cudaFuncAttributeMaxDynamicSharedMemorySize,
                             (128 * MPIT * 2 + 256 * MPIT * 2) * (int)sizeof(float));
        cudaFuncSetAttribute(ykernel23, cudaFuncAttributeMaxDynamicSharedMemorySize,
                             (6912 + 12 * 49) * (int)sizeof(float2));
        cudaStreamCreateWithFlags(&s2, cudaStreamNonBlocking);
        cudaEventCreateWithFlags(&evFork, cudaEventDisableTiming);
        cudaEventCreateWithFlags(&evY,    cudaEventDisableTiming);
    }
    const float* x  = (const float*)d_in[0];   // [8,16,48,48,48]
    const float* wt = (const float*)d_in[2];   // [16,16,12,12,12]
    float* out = (float*)d_out;

    const int mix_smem = (128 * MPIT * 2 + 256 * MPIT * 2) * (int)sizeof(float);
    const int mix_grid = NHALF / MK + 1;       // 3457
    const int y_smem   = (6912 + 12 * 49) * (int)sizeof(float2);

    init_tw<<<(L * L + 255) / 256, 256>>>();

    // fork: Y path on side stream, overlapped with forward X passes
    cudaEventRecord(evFork, 0);
    cudaStreamWaitEvent(s2, evFork, 0);
    ykernel1<<<(CF * 12 * 12 * L + 255) / 256, 256, 0, s2>>>(wt);
    ykernel23<<<CF * 4, 256, y_smem, s2>>>();
    cudaEventRecord(evY, s2);

    // forward: x -> Xh (main stream)
    pass_wh<<<BF * L, 256>>>(x, bufB);
    pass_d <<<BF * L, 256>>>(bufB, xh, 1.f);

    // join: mix needs Yh
    cudaStreamWaitEvent(0, evY, 0);
    mix5<<<mix_grid, 256, mix_smem>>>();

    // inverse: Z -> out (scaled 1/N3)
    pass_wh<<<BF * L, 256>>>(z, bufB);
    pass_d <<<BF * L, 256>>>(bufB, out, 1.f / (float)N3);
}